// round 4
// baseline (speedup 1.0000x reference)
#include <cuda_runtime.h>
#include <math.h>

#define SEQ   2048
#define BATCH 2
#define EMBED 1024
#define HEADS 16
#define HDIM  64
#define FFN   4096
#define TOK   (BATCH*SEQ)   /* 4096 tokens */

// ---------------- scratch (device globals; no allocations allowed) ----------
static __device__ float g_q [TOK*EMBED];
static __device__ float g_k [TOK*EMBED];
static __device__ float g_v [TOK*EMBED];
static __device__ float g_o [TOK*EMBED];
static __device__ float g_t1[TOK*EMBED];
static __device__ float g_x1[TOK*EMBED];
static __device__ float g_ff[(size_t)TOK*FFN];
static __device__ float g_t2[TOK*EMBED];
// transposed weights (k-major for tensor-core GEMM B operand)
static __device__ float g_woT[3*EMBED*EMBED];
static __device__ float g_w1T[(size_t)3*EMBED*FFN];
static __device__ float g_w2T[(size_t)3*FFN*EMBED];

// ---------------------------------------------------------------------------
// 32x32 tiled transpose: dst[c][r] = src[r][c], per-layer via blockIdx.z
// ---------------------------------------------------------------------------
__global__ __launch_bounds__(256)
void transpose_k(const float* __restrict__ src, float* __restrict__ dst, int R, int C)
{
    __shared__ float t[32][33];
    const float* s = src + (size_t)blockIdx.z * R * C;
    float*       d = dst + (size_t)blockIdx.z * R * C;
    int x  = blockIdx.x*32 + threadIdx.x;
    int y0 = blockIdx.y*32;
    #pragma unroll
    for (int j = 0; j < 4; j++)
        t[threadIdx.y + 8*j][threadIdx.x] = s[(size_t)(y0 + threadIdx.y + 8*j)*C + x];
    __syncthreads();
    int x2 = blockIdx.y*32 + threadIdx.x;
    int y2 = blockIdx.x*32;
    #pragma unroll
    for (int j = 0; j < 4; j++)
        d[(size_t)(y2 + threadIdx.y + 8*j)*R + x2] = t[threadIdx.x][threadIdx.y + 8*j];
}

// ---------------------------------------------------------------------------
// tf32 helpers
// ---------------------------------------------------------------------------
__device__ __forceinline__ unsigned f2tf(float x) {
    unsigned r;
    asm("cvt.rna.tf32.f32 %0, %1;" : "=r"(r) : "f"(x));
    return r;
}
__device__ __forceinline__ void mma_tf32(float* d, const unsigned* a, const unsigned* b) {
    asm volatile(
        "mma.sync.aligned.m16n8k8.row.col.f32.tf32.tf32.f32 "
        "{%0,%1,%2,%3}, {%4,%5,%6,%7}, {%8,%9}, {%0,%1,%2,%3};\n"
        : "+f"(d[0]), "+f"(d[1]), "+f"(d[2]), "+f"(d[3])
        : "r"(a[0]), "r"(a[1]), "r"(a[2]), "r"(a[3]), "r"(b[0]), "r"(b[1]));
}

// ---------------------------------------------------------------------------
// tf32 tensor-core GEMM: C = A(MxK, row-major) @ B  where BT is B transposed,
// i.e. BT[n][k] row-major.  + bias[N], optional ReLU.
// BM=BN=128, BK=32; 256 threads = 8 warps (4x2), warp tile 32x64.
// Dynamic smem: 2 stages x (As[128][36] + Bs[128][36]) = 73728 bytes.
// ---------------------------------------------------------------------------
#define LDT 36
#define STG_F (128*LDT)

template<int RELU>
__global__ __launch_bounds__(256, 1)
void gemm_tf32(const float* __restrict__ A, const float* __restrict__ BT,
               const float* __restrict__ bias, float* __restrict__ C,
               int M, int N, int K)
{
    extern __shared__ float smem[];
    float* As = smem;                 // [2][128][LDT]
    float* Bs = smem + 2*STG_F;       // [2][128][LDT]

    const int tid  = threadIdx.x;
    const int lane = tid & 31, warp = tid >> 5;
    const int g  = lane >> 2, t4 = lane & 3;
    const int m0w = (warp >> 1) * 32;
    const int n0w = (warp & 1) * 64;
    const int rowBase = blockIdx.y * 128;
    const int colBase = blockIdx.x * 128;

    const int lr  = tid >> 1;           // loader row 0..127
    const int lo  = (tid & 1) * 16;     // k offset 0/16
    const float* Ag = A  + (size_t)(rowBase + lr)*K + lo;
    const float* Bg = BT + (size_t)(colBase + lr)*K + lo;

    float acc[2][8][4];
    #pragma unroll
    for (int mi = 0; mi < 2; mi++)
        #pragma unroll
        for (int ni = 0; ni < 8; ni++)
            #pragma unroll
            for (int r = 0; r < 4; r++) acc[mi][ni][r] = 0.f;

    float4 pa[4], pb[4];

    // prologue: load iter 0
    #pragma unroll
    for (int u = 0; u < 4; u++) {
        pa[u] = *(const float4*)(Ag + 4*u);
        pb[u] = *(const float4*)(Bg + 4*u);
    }
    {
        float* ap = &As[lr*LDT + lo];
        float* bp = &Bs[lr*LDT + lo];
        #pragma unroll
        for (int u = 0; u < 4; u++) {
            float4 ca, cb;
            ca.x = __uint_as_float(f2tf(pa[u].x)); ca.y = __uint_as_float(f2tf(pa[u].y));
            ca.z = __uint_as_float(f2tf(pa[u].z)); ca.w = __uint_as_float(f2tf(pa[u].w));
            cb.x = __uint_as_float(f2tf(pb[u].x)); cb.y = __uint_as_float(f2tf(pb[u].y));
            cb.z = __uint_as_float(f2tf(pb[u].z)); cb.w = __uint_as_float(f2tf(pb[u].w));
            *(float4*)(ap + 4*u) = ca;
            *(float4*)(bp + 4*u) = cb;
        }
    }
    __syncthreads();

    const int NIT = K >> 5;
    for (int it = 0; it < NIT; it++) {
        const int cur = it & 1;
        // prefetch next tile to registers
        if (it + 1 < NIT) {
            const float* ag = Ag + (it+1)*32;
            const float* bg = Bg + (it+1)*32;
            #pragma unroll
            for (int u = 0; u < 4; u++) {
                pa[u] = *(const float4*)(ag + 4*u);
                pb[u] = *(const float4*)(bg + 4*u);
            }
        }

        const float* as = As + cur*STG_F;
        const float* bs = Bs + cur*STG_F;
        #pragma unroll
        for (int ks = 0; ks < 4; ks++) {
            const int kk = ks*8 + t4;
            unsigned a[2][4], b[8][2];
            #pragma unroll
            for (int mi = 0; mi < 2; mi++) {
                const int m = m0w + mi*16 + g;
                a[mi][0] = __float_as_uint(as[(m    )*LDT + kk    ]);
                a[mi][1] = __float_as_uint(as[(m + 8)*LDT + kk    ]);
                a[mi][2] = __float_as_uint(as[(m    )*LDT + kk + 4]);
                a[mi][3] = __float_as_uint(as[(m + 8)*LDT + kk + 4]);
            }
            #pragma unroll
            for (int ni = 0; ni < 8; ni++) {
                const int n = n0w + ni*8 + g;
                b[ni][0] = __float_as_uint(bs[n*LDT + kk    ]);
                b[ni][1] = __float_as_uint(bs[n*LDT + kk + 4]);
            }
            #pragma unroll
            for (int mi = 0; mi < 2; mi++)
                #pragma unroll
                for (int ni = 0; ni < 8; ni++)
                    mma_tf32(acc[mi][ni], a[mi], b[ni]);
        }

        if (it + 1 < NIT) {
            float* ap = &As[(cur^1)*STG_F + lr*LDT + lo];
            float* bp = &Bs[(cur^1)*STG_F + lr*LDT + lo];
            #pragma unroll
            for (int u = 0; u < 4; u++) {
                float4 ca, cb;
                ca.x = __uint_as_float(f2tf(pa[u].x)); ca.y = __uint_as_float(f2tf(pa[u].y));
                ca.z = __uint_as_float(f2tf(pa[u].z)); ca.w = __uint_as_float(f2tf(pa[u].w));
                cb.x = __uint_as_float(f2tf(pb[u].x)); cb.y = __uint_as_float(f2tf(pb[u].y));
                cb.z = __uint_as_float(f2tf(pb[u].z)); cb.w = __uint_as_float(f2tf(pb[u].w));
                *(float4*)(ap + 4*u) = ca;
                *(float4*)(bp + 4*u) = cb;
            }
        }
        __syncthreads();
    }

    // epilogue
    #pragma unroll
    for (int mi = 0; mi < 2; mi++) {
        const int r0 = rowBase + m0w + mi*16 + g;
        #pragma unroll
        for (int ni = 0; ni < 8; ni++) {
            const int c = colBase + n0w + ni*8 + t4*2;
            float b0 = bias[c], b1 = bias[c+1];
            float v0 = acc[mi][ni][0] + b0;
            float v1 = acc[mi][ni][1] + b1;
            float v2 = acc[mi][ni][2] + b0;
            float v3 = acc[mi][ni][3] + b1;
            if (RELU) {
                v0 = fmaxf(v0, 0.f); v1 = fmaxf(v1, 0.f);
                v2 = fmaxf(v2, 0.f); v3 = fmaxf(v3, 0.f);
            }
            *(float2*)&C[(size_t)r0*N + c]       = make_float2(v0, v1);
            *(float2*)&C[(size_t)(r0+8)*N + c]   = make_float2(v2, v3);
        }
    }
}

// ---------------------------------------------------------------------------
// Embed: out[t,:] = x[t,:] @ W(64x1024) + b + pe[s,:]
// ---------------------------------------------------------------------------
__global__ __launch_bounds__(256)
void embed_kernel(const float* __restrict__ X, const float* __restrict__ W,
                  const float* __restrict__ bias, const float* __restrict__ pe,
                  float* __restrict__ out)
{
    __shared__ float Xs[64][64];
    __shared__ float Ws[64][64];
    const int tid = threadIdx.x;
    const int tx = tid & 15, ty = tid >> 4;
    const int t0 = blockIdx.x * 64;
    const int c0 = blockIdx.y * 64;

    {
        const int r = tid >> 2, o4 = (tid & 3) * 16;
        const float* xp = X + (size_t)(t0 + r) * 64 + o4;
        const float* wp = W + (size_t)r * EMBED + c0 + o4;
        #pragma unroll
        for (int u = 0; u < 4; u++) {
            *(float4*)&Xs[r][o4 + 4*u] = *(const float4*)(xp + 4*u);
            *(float4*)&Ws[r][o4 + 4*u] = *(const float4*)(wp + 4*u);
        }
    }
    __syncthreads();

    float acc[4][4];
    #pragma unroll
    for (int i = 0; i < 4; i++)
        #pragma unroll
        for (int j = 0; j < 4; j++) acc[i][j] = 0.f;

    #pragma unroll 8
    for (int d = 0; d < 64; d++) {
        float4 wv = *(const float4*)&Ws[d][tx*4];
        #pragma unroll
        for (int i = 0; i < 4; i++) {
            float xr = Xs[ty*4 + i][d];
            acc[i][0] += xr * wv.x;
            acc[i][1] += xr * wv.y;
            acc[i][2] += xr * wv.z;
            acc[i][3] += xr * wv.w;
        }
    }

    float4 bv = *(const float4*)(bias + c0 + tx*4);
    #pragma unroll
    for (int i = 0; i < 4; i++) {
        int t = t0 + ty*4 + i;
        int s = t & (SEQ - 1);
        float4 pv = *(const float4*)(pe + (size_t)s*EMBED + c0 + tx*4);
        float4 r;
        r.x = acc[i][0] + bv.x + pv.x;
        r.y = acc[i][1] + bv.y + pv.y;
        r.z = acc[i][2] + bv.z + pv.z;
        r.w = acc[i][3] + bv.w + pv.w;
        *(float4*)(out + (size_t)t*EMBED + c0 + tx*4) = r;
    }
}

// ---------------------------------------------------------------------------
// QKV per-head 64x64 projections, writes [B,H,S,D]
// ---------------------------------------------------------------------------
__global__ __launch_bounds__(256)
void qkv_kernel(const float* __restrict__ H,
                const float* __restrict__ Wq, const float* __restrict__ Wk,
                const float* __restrict__ Wv,
                float* __restrict__ Q, float* __restrict__ K, float* __restrict__ V)
{
    __shared__ float Xs[64][64];
    __shared__ float Ws[64][64];
    const int tid = threadIdx.x;
    const int tx = tid & 15, ty = tid >> 4;
    const int t0 = blockIdx.x * 64;
    const int hh = blockIdx.y;

    const int r = tid >> 2, o4 = (tid & 3) * 16;
    {
        const float* hp = H + (size_t)(t0 + r) * EMBED + hh*HDIM + o4;
        #pragma unroll
        for (int u = 0; u < 4; u++)
            *(float4*)&Xs[r][o4 + 4*u] = *(const float4*)(hp + 4*u);
    }

    const float* Wlist[3] = {Wq, Wk, Wv};
    float*       Olist[3] = {Q, K, V};

    for (int m = 0; m < 3; m++) {
        __syncthreads();
        {
            const float* wp = Wlist[m] + (size_t)r * 64 + o4;
            #pragma unroll
            for (int u = 0; u < 4; u++)
                *(float4*)&Ws[r][o4 + 4*u] = *(const float4*)(wp + 4*u);
        }
        __syncthreads();

        float acc[4][4];
        #pragma unroll
        for (int i = 0; i < 4; i++)
            #pragma unroll
            for (int j = 0; j < 4; j++) acc[i][j] = 0.f;

        #pragma unroll 8
        for (int d = 0; d < 64; d++) {
            float4 wv = *(const float4*)&Ws[d][tx*4];
            #pragma unroll
            for (int i = 0; i < 4; i++) {
                float xr = Xs[ty*4 + i][d];
                acc[i][0] += xr * wv.x;
                acc[i][1] += xr * wv.y;
                acc[i][2] += xr * wv.z;
                acc[i][3] += xr * wv.w;
            }
        }

        #pragma unroll
        for (int i = 0; i < 4; i++) {
            int t = t0 + ty*4 + i;
            int n = t >> 11;
            int s = t & (SEQ - 1);
            float* op = Olist[m] + ((size_t)(n*HEADS + hh)*SEQ + s)*HDIM + tx*4;
            *(float4*)op = make_float4(acc[i][0], acc[i][1], acc[i][2], acc[i][3]);
        }
    }
}

// ---------------------------------------------------------------------------
// Flash attention (all-ones mask), fp32 SIMT
// ---------------------------------------------------------------------------
__global__ __launch_bounds__(256)
void attn_kernel(const float* __restrict__ Q, const float* __restrict__ K,
                 const float* __restrict__ V, float* __restrict__ O)
{
    __shared__ float Qs[64][64];
    __shared__ float Ks[64][64];
    __shared__ float Vs[64][64];

    const int tid = threadIdx.x;
    const int tx = tid & 15, ty = tid >> 4;
    const int qt = blockIdx.x, bh = blockIdx.y;
    const int lr = tid >> 2;
    const int lc = (tid & 3) * 16;

    {
        const float* p = Q + ((size_t)bh * SEQ + qt*64) * HDIM + (size_t)lr*HDIM + lc;
        #pragma unroll
        for (int u = 0; u < 4; u++) {
            float4 v = *(const float4*)(p + 4*u);
            Qs[lc + 4*u + 0][lr] = v.x;
            Qs[lc + 4*u + 1][lr] = v.y;
            Qs[lc + 4*u + 2][lr] = v.z;
            Qs[lc + 4*u + 3][lr] = v.w;
        }
    }

    float m[4], l[4], o[4][4];
    #pragma unroll
    for (int i = 0; i < 4; i++) {
        m[i] = -3.0e38f; l[i] = 0.f;
        #pragma unroll
        for (int j = 0; j < 4; j++) o[i][j] = 0.f;
    }

    for (int kt = 0; kt < SEQ/64; kt++) {
        __syncthreads();
        {
            const float* pk = K + ((size_t)bh*SEQ + kt*64)*HDIM + (size_t)lr*HDIM + lc;
            const float* pv = V + ((size_t)bh*SEQ + kt*64)*HDIM + (size_t)lr*HDIM + lc;
            #pragma unroll
            for (int u = 0; u < 4; u++) {
                float4 kv = *(const float4*)(pk + 4*u);
                Ks[lc + 4*u + 0][lr] = kv.x;
                Ks[lc + 4*u + 1][lr] = kv.y;
                Ks[lc + 4*u + 2][lr] = kv.z;
                Ks[lc + 4*u + 3][lr] = kv.w;
                *(float4*)&Vs[lr][lc + 4*u] = *(const float4*)(pv + 4*u);
            }
        }
        __syncthreads();

        float s[4][4];
        #pragma unroll
        for (int i = 0; i < 4; i++)
            #pragma unroll
            for (int j = 0; j < 4; j++) s[i][j] = 0.f;

        #pragma unroll 8
        for (int d = 0; d < 64; d++) {
            float4 qv = *(const float4*)&Qs[d][ty*4];
            float4 kv = *(const float4*)&Ks[d][tx*4];
            s[0][0] += qv.x*kv.x; s[0][1] += qv.x*kv.y; s[0][2] += qv.x*kv.z; s[0][3] += qv.x*kv.w;
            s[1][0] += qv.y*kv.x; s[1][1] += qv.y*kv.y; s[1][2] += qv.y*kv.z; s[1][3] += qv.y*kv.w;
            s[2][0] += qv.z*kv.x; s[2][1] += qv.z*kv.y; s[2][2] += qv.z*kv.z; s[2][3] += qv.z*kv.w;
            s[3][0] += qv.w*kv.x; s[3][1] += qv.w*kv.y; s[3][2] += qv.w*kv.z; s[3][3] += qv.w*kv.w;
        }

        const float SCALE = 0.03125f;
        #pragma unroll
        for (int i = 0; i < 4; i++) {
            #pragma unroll
            for (int j = 0; j < 4; j++) s[i][j] *= SCALE;
            float rm = fmaxf(fmaxf(s[i][0], s[i][1]), fmaxf(s[i][2], s[i][3]));
            rm = fmaxf(rm, __shfl_xor_sync(0xffffffffu, rm, 8));
            rm = fmaxf(rm, __shfl_xor_sync(0xffffffffu, rm, 4));
            rm = fmaxf(rm, __shfl_xor_sync(0xffffffffu, rm, 2));
            rm = fmaxf(rm, __shfl_xor_sync(0xffffffffu, rm, 1));
            float nm  = fmaxf(m[i], rm);
            float fac = __expf(m[i] - nm);
            float rs = 0.f;
            #pragma unroll
            for (int j = 0; j < 4; j++) { s[i][j] = __expf(s[i][j] - nm); rs += s[i][j]; }
            rs += __shfl_xor_sync(0xffffffffu, rs, 8);
            rs += __shfl_xor_sync(0xffffffffu, rs, 4);
            rs += __shfl_xor_sync(0xffffffffu, rs, 2);
            rs += __shfl_xor_sync(0xffffffffu, rs, 1);
            l[i] = l[i]*fac + rs;
            m[i] = nm;
            #pragma unroll
            for (int j = 0; j < 4; j++) o[i][j] *= fac;
        }

        __syncthreads();
        float (*Ps)[64] = Ks;
        #pragma unroll
        for (int i = 0; i < 4; i++)
            #pragma unroll
            for (int j = 0; j < 4; j++) Ps[ty*4 + i][tx*4 + j] = s[i][j];
        __syncthreads();

        #pragma unroll 8
        for (int k = 0; k < 64; k++) {
            float4 vv = *(const float4*)&Vs[k][tx*4];
            #pragma unroll
            for (int i = 0; i < 4; i++) {
                float pk = Ps[ty*4 + i][k];
                o[i][0] += pk*vv.x;
                o[i][1] += pk*vv.y;
                o[i][2] += pk*vv.z;
                o[i][3] += pk*vv.w;
            }
        }
    }

    const int n = bh >> 4, hh = bh & 15;
    #pragma unroll
    for (int i = 0; i < 4; i++) {
        float inv = 1.f / l[i];
        int t = n*SEQ + qt*64 + ty*4 + i;
        float* op = O + (size_t)t*EMBED + hh*HDIM + tx*4;
        *(float4*)op = make_float4(o[i][0]*inv, o[i][1]*inv, o[i][2]*inv, o[i][3]*inv);
    }
}

// ---------------------------------------------------------------------------
// Fused residual + LayerNorm
// ---------------------------------------------------------------------------
__global__ __launch_bounds__(256)
void ln_kernel(const float* __restrict__ A, const float* __restrict__ R,
               const float* __restrict__ gma, const float* __restrict__ bta,
               float* __restrict__ out)
{
    __shared__ float s1[8], s2[8];
    const int t = blockIdx.x, tid = threadIdx.x;
    const size_t base = (size_t)t * EMBED + tid * 4;

    float4 a = *(const float4*)(A + base);
    float4 r = *(const float4*)(R + base);
    float v0 = a.x + r.x, v1 = a.y + r.y, v2 = a.z + r.z, v3 = a.w + r.w;
    float sum = v0 + v1 + v2 + v3;
    float sq  = v0*v0 + v1*v1 + v2*v2 + v3*v3;

    #pragma unroll
    for (int off = 16; off > 0; off >>= 1) {
        sum += __shfl_xor_sync(0xffffffffu, sum, off);
        sq  += __shfl_xor_sync(0xffffffffu, sq,  off);
    }
    if ((tid & 31) == 0) { s1[tid >> 5] = sum; s2[tid >> 5] = sq; }
    __syncthreads();
    if (tid < 32) {
        float ss = (tid < 8) ? s1[tid] : 0.f;
        float qq = (tid < 8) ? s2[tid] : 0.f;
        #pragma unroll
        for (int off = 4; off > 0; off >>= 1) {
            ss += __shfl_xor_sync(0xffffffffu, ss, off);
            qq += __shfl_xor_sync(0xffffffffu, qq, off);
        }
        if (tid == 0) { s1[0] = ss; s2[0] = qq; }
    }
    __syncthreads();

    const float inv = 1.f / (float)EMBED;
    float mu  = s1[0] * inv;
    float var = s2[0] * inv - mu*mu;
    float rstd = rsqrtf(var + 1e-5f);

    float4 g = *(const float4*)(gma + tid*4);
    float4 b = *(const float4*)(bta + tid*4);
    float4 o;
    o.x = (v0 - mu)*rstd*g.x + b.x;
    o.y = (v1 - mu)*rstd*g.y + b.y;
    o.z = (v2 - mu)*rstd*g.z + b.z;
    o.w = (v3 - mu)*rstd*g.w + b.w;
    *(float4*)(out + base) = o;
}

// ---------------------------------------------------------------------------
extern "C" void kernel_launch(void* const* d_in, const int* in_sizes, int n_in,
                              void* d_out, int out_size)
{
    const float* x       = (const float*)d_in[0];
    // d_in[1] = mask: all-true -> no-op
    const float* embed_W = (const float*)d_in[2];
    const float* embed_b = (const float*)d_in[3];
    const float* pe      = (const float*)d_in[4];
    const float* Wq      = (const float*)d_in[5];
    const float* Wk      = (const float*)d_in[6];
    const float* Wv      = (const float*)d_in[7];
    const float* Wo      = (const float*)d_in[8];
    const float* bo      = (const float*)d_in[9];
    const float* ln1_g   = (const float*)d_in[10];
    const float* ln1_b   = (const float*)d_in[11];
    const float* W1      = (const float*)d_in[12];
    const float* b1      = (const float*)d_in[13];
    const float* W2      = (const float*)d_in[14];
    const float* b2      = (const float*)d_in[15];
    const float* ln2_g   = (const float*)d_in[16];
    const float* ln2_b   = (const float*)d_in[17];
    float* h = (float*)d_out;

    float *q, *k, *v, *o, *t1, *x1, *ff, *t2, *woT, *w1T, *w2T;
    cudaGetSymbolAddress((void**)&q,   g_q);
    cudaGetSymbolAddress((void**)&k,   g_k);
    cudaGetSymbolAddress((void**)&v,   g_v);
    cudaGetSymbolAddress((void**)&o,   g_o);
    cudaGetSymbolAddress((void**)&t1,  g_t1);
    cudaGetSymbolAddress((void**)&x1,  g_x1);
    cudaGetSymbolAddress((void**)&ff,  g_ff);
    cudaGetSymbolAddress((void**)&t2,  g_t2);
    cudaGetSymbolAddress((void**)&woT, g_woT);
    cudaGetSymbolAddress((void**)&w1T, g_w1T);
    cudaGetSymbolAddress((void**)&w2T, g_w2T);

    const int SMEM_GEMM = 4 * STG_F * (int)sizeof(float);   // 73728
    cudaFuncSetAttribute(gemm_tf32<0>, cudaFuncAttributeMaxDynamicSharedMemorySize, SMEM_GEMM);
    cudaFuncSetAttribute(gemm_tf32<1>, cudaFuncAttributeMaxDynamicSharedMemorySize, SMEM_GEMM);

    // weight transposes (k-major B for the mma GEMMs)
    transpose_k<<<dim3(EMBED/32, EMBED/32, 3), dim3(32,8)>>>(Wo, woT, EMBED, EMBED);
    transpose_k<<<dim3(FFN/32,   EMBED/32, 3), dim3(32,8)>>>(W1, w1T, EMBED, FFN);
    transpose_k<<<dim3(EMBED/32, FFN/32,   3), dim3(32,8)>>>(W2, w2T, FFN, EMBED);

    embed_kernel<<<dim3(TOK/64, EMBED/64), 256>>>(x, embed_W, embed_b, pe, h);

    for (int l = 0; l < 3; l++) {
        qkv_kernel<<<dim3(TOK/64, HEADS), 256>>>(
            h, Wq + l*HDIM*HDIM, Wk + l*HDIM*HDIM, Wv + l*HDIM*HDIM, q, k, v);

        attn_kernel<<<dim3(SEQ/64, BATCH*HEADS), 256>>>(q, k, v, o);

        gemm_tf32<0><<<dim3(EMBED/128, TOK/128), 256, SMEM_GEMM>>>(
            o, woT + (size_t)l*EMBED*EMBED, bo + l*EMBED, t1, TOK, EMBED, EMBED);

        ln_kernel<<<TOK, 256>>>(t1, h, ln1_g + l*EMBED, ln1_b + l*EMBED, x1);

        gemm_tf32<1><<<dim3(FFN/128, TOK/128), 256, SMEM_GEMM>>>(
            x1, w1T + (size_t)l*EMBED*FFN, b1 + l*FFN, ff, TOK, FFN, EMBED);

        gemm_tf32<0><<<dim3(EMBED/128, TOK/128), 256, SMEM_GEMM>>>(
            ff, w2T + (size_t)l*FFN*EMBED, b2 + l*EMBED, t2, TOK, EMBED, FFN);

        ln_kernel<<<TOK, 256>>>(t2, x1, ln2_g + l*EMBED, ln2_b + l*EMBED, h);
    }
}

// round 9
// speedup vs baseline: 2.1991x; 2.1991x over previous
#include <cuda_runtime.h>
#include <cuda_fp16.h>
#include <math.h>
#include <stdint.h>

#define SEQ   2048
#define BATCH 2
#define EMBED 1024
#define HEADS 16
#define HDIM  64
#define FFN   4096
#define TOK   (BATCH*SEQ)   /* 4096 tokens */

// ---------------- scratch (device globals; no allocations allowed) ----------
static __device__ float  g_q  [TOK*EMBED];
static __device__ float  g_k  [TOK*EMBED];
static __device__ float  g_v  [TOK*EMBED];
static __device__ float  g_t1 [TOK*EMBED];
static __device__ float  g_x1 [TOK*EMBED];
static __device__ float  g_t2 [TOK*EMBED];
static __device__ __half g_oh [TOK*EMBED];            // attn out (GEMM A)
static __device__ __half g_x1h[TOK*EMBED];            // ln1 out (GEMM A)
static __device__ __half g_ffh[(size_t)TOK*FFN];      // relu(ffn1) (GEMM A)
static __device__ __half g_woT[3*EMBED*EMBED];        // half, k-major BT[n][k]
static __device__ __half g_w1T[(size_t)3*EMBED*FFN];
static __device__ __half g_w2T[(size_t)3*FFN*EMBED];

// ---------------------------------------------------------------------------
// helpers
// ---------------------------------------------------------------------------
__device__ __forceinline__ uint32_t smem_u32(const void* p) {
    uint32_t a;
    asm("{ .reg .u64 t; cvta.to.shared.u64 t, %1; cvt.u32.u64 %0, t; }"
        : "=r"(a) : "l"(p));
    return a;
}
__device__ __forceinline__ void ldsm_x4(unsigned* r, uint32_t addr) {
    asm volatile("ldmatrix.sync.aligned.m8n8.x4.shared.b16 {%0,%1,%2,%3}, [%4];"
                 : "=r"(r[0]), "=r"(r[1]), "=r"(r[2]), "=r"(r[3]) : "r"(addr));
}
__device__ __forceinline__ void mma16816(float* c, const unsigned* a, const unsigned* b) {
    asm volatile(
        "mma.sync.aligned.m16n8k16.row.col.f32.f16.f16.f32 "
        "{%0,%1,%2,%3}, {%4,%5,%6,%7}, {%8,%9}, {%0,%1,%2,%3};"
        : "+f"(c[0]), "+f"(c[1]), "+f"(c[2]), "+f"(c[3])
        : "r"(a[0]), "r"(a[1]), "r"(a[2]), "r"(a[3]), "r"(b[0]), "r"(b[1]));
}
// pack two fp32 into f16x2: lo = x, hi = y
__device__ __forceinline__ uint32_t pack_h2(float x, float y) {
    uint32_t r;
    asm("cvt.rn.f16x2.f32 %0, %1, %2;" : "=r"(r) : "f"(y), "f"(x));
    return r;
}
#define CP_ASYNC16(dst, src) \
    asm volatile("cp.async.cg.shared.global [%0], [%1], 16;" :: "r"(dst), "l"(src) : "memory")
#define CP_COMMIT()  asm volatile("cp.async.commit_group;" ::: "memory")
#define CP_WAIT(n)   asm volatile("cp.async.wait_group %0;" :: "n"(n) : "memory")

// ---------------------------------------------------------------------------
// fp16 mma.sync GEMM: C(MxN) = A(MxK,row-major,half) @ B, BT[n][k] half.
// CTA tile 128x128, k-chunk 32. 8 warps (2m x 4n), warp tile 64x32.
// smem: half [2 stages][128][56] per operand; cp.async double-buffer pipeline.
// ---------------------------------------------------------------------------
#define SSTR   56
#define STG_B  (128*SSTR*2)          /* 14336 bytes per operand stage */
#define GEMM_DSMEM (4*STG_B)         /* 57344 */

template<int RELU, int OUT_HALF>
__global__ __launch_bounds__(256, 2)
void gemm_hmma(const __half* __restrict__ A, const __half* __restrict__ BT,
               const float* __restrict__ bias, void* __restrict__ Cv,
               int M, int N, int K)
{
    extern __shared__ __align__(16) char dsm[];
    const int tid  = threadIdx.x;
    const int lane = tid & 31, warp = tid >> 5;
    const int m0w = (warp >> 2) * 64;
    const int n0w = (warp & 3) * 32;
    const int rowBase = blockIdx.y * 128;
    const int colBase = blockIdx.x * 128;

    const uint32_t sb = smem_u32(dsm);
    const uint32_t aS = sb;                 // A stages: +0, +STG_B
    const uint32_t bS = sb + 2*STG_B;       // B stages

    // loader: row lr (0..127), halves offset lo (0/16) within 32-half chunk
    const int lr = tid >> 1, lo = (tid & 1) * 16;
    const __half* Ag = A  + (size_t)(rowBase + lr) * K + lo;
    const __half* Bg = BT + (size_t)(colBase + lr) * K + lo;
    const uint32_t stOff = lr*(SSTR*2) + lo*2;     // byte offset in stage

    float acc[4][4][4];
    #pragma unroll
    for (int mt = 0; mt < 4; mt++)
        #pragma unroll
        for (int nt = 0; nt < 4; nt++)
            #pragma unroll
            for (int r = 0; r < 4; r++) acc[mt][nt][r] = 0.f;

    #define ISSUE(c, stg)                                   \
    {                                                       \
        const __half* ag = Ag + (size_t)(c)*32;             \
        const __half* bg = Bg + (size_t)(c)*32;             \
        uint32_t ad = aS + (stg)*STG_B + stOff;             \
        uint32_t bd = bS + (stg)*STG_B + stOff;             \
        CP_ASYNC16(ad,      ag);                            \
        CP_ASYNC16(ad + 16, ag + 8);                        \
        CP_ASYNC16(bd,      bg);                            \
        CP_ASYNC16(bd + 16, bg + 8);                        \
        CP_COMMIT();                                        \
    }

    ISSUE(0, 0);

    // fragment address components
    const uint32_t aRow  = m0w + (lane & 15);          // + mt*16
    const uint32_t aColB = ((lane >> 4) * 8) * 2;      // bytes
    const uint32_t bRowB = (n0w + (lane >> 2)) * (SSTR*2);
    const uint32_t bColB = (lane & 3) * 4;             // bytes

    const int NC = K >> 5;
    for (int c = 0; c < NC; c++) {
        const int cur = c & 1;
        if (c + 1 < NC) { ISSUE(c + 1, cur ^ 1); CP_WAIT(1); }
        else            { CP_WAIT(0); }
        __syncthreads();

        const uint32_t aSt = aS + cur*STG_B;
        const char*    bPt = dsm + 2*STG_B + cur*STG_B + bRowB + bColB;
        #pragma unroll
        for (int s = 0; s < 2; s++) {
            const uint32_t k0B = s * 32;               // 16 halves = 32 bytes
            unsigned af[4][4], bf[4][2];
            #pragma unroll
            for (int mt = 0; mt < 4; mt++)
                ldsm_x4(af[mt], aSt + (aRow + mt*16)*(SSTR*2) + k0B + aColB);
            #pragma unroll
            for (int nt = 0; nt < 4; nt++) {
                const char* nb = bPt + nt*8*(SSTR*2) + k0B;
                bf[nt][0] = *(const unsigned*)(nb);
                bf[nt][1] = *(const unsigned*)(nb + 16);
            }
            #pragma unroll
            for (int mt = 0; mt < 4; mt++)
                #pragma unroll
                for (int nt = 0; nt < 4; nt++)
                    mma16816(acc[mt][nt], af[mt], bf[nt]);
        }
        __syncthreads();
    }
    #undef ISSUE

    // epilogue: rows m0w+mt*16+(lane>>2)(+8), cols n0w+nt*8+(lane&3)*2
    const int er = lane >> 2, ec = (lane & 3) * 2;
    #pragma unroll
    for (int mt = 0; mt < 4; mt++) {
        const int row = rowBase + m0w + mt*16 + er;
        #pragma unroll
        for (int nt = 0; nt < 4; nt++) {
            const int col = colBase + n0w + nt*8 + ec;
            float2 bv = *(const float2*)(bias + col);
            float v0 = acc[mt][nt][0] + bv.x;
            float v1 = acc[mt][nt][1] + bv.y;
            float v2 = acc[mt][nt][2] + bv.x;
            float v3 = acc[mt][nt][3] + bv.y;
            if (RELU) {
                v0 = fmaxf(v0, 0.f); v1 = fmaxf(v1, 0.f);
                v2 = fmaxf(v2, 0.f); v3 = fmaxf(v3, 0.f);
            }
            if (OUT_HALF) {
                __half* C = (__half*)Cv;
                *(unsigned*)&C[(size_t)row*N + col]     = pack_h2(v0, v1);
                *(unsigned*)&C[(size_t)(row+8)*N + col] = pack_h2(v2, v3);
            } else {
                float* C = (float*)Cv;
                *(float2*)&C[(size_t)row*N + col]     = make_float2(v0, v1);
                *(float2*)&C[(size_t)(row+8)*N + col] = make_float2(v2, v3);
            }
        }
    }
}

// ---------------------------------------------------------------------------
// 32x32 tiled transpose + fp16 convert: dst[c][r] = (half)src[r][c]
// ---------------------------------------------------------------------------
__global__ __launch_bounds__(256)
void transpose_h(const float* __restrict__ src, __half* __restrict__ dst, int R, int C)
{
    __shared__ float t[32][33];
    const float* s = src + (size_t)blockIdx.z * R * C;
    __half*      d = dst + (size_t)blockIdx.z * R * C;
    int x  = blockIdx.x*32 + threadIdx.x;
    int y0 = blockIdx.y*32;
    #pragma unroll
    for (int j = 0; j < 4; j++)
        t[threadIdx.y + 8*j][threadIdx.x] = s[(size_t)(y0 + threadIdx.y + 8*j)*C + x];
    __syncthreads();
    int x2 = blockIdx.y*32 + threadIdx.x;
    int y2 = blockIdx.x*32;
    #pragma unroll
    for (int j = 0; j < 4; j++)
        d[(size_t)(y2 + threadIdx.y + 8*j)*R + x2] = __float2half(t[threadIdx.x][threadIdx.y + 8*j]);
}

// ---------------------------------------------------------------------------
// Embed: out[t,:] = x[t,:] @ W(64x1024) + b + pe[s,:]
// ---------------------------------------------------------------------------
__global__ __launch_bounds__(256)
void embed_kernel(const float* __restrict__ X, const float* __restrict__ W,
                  const float* __restrict__ bias, const float* __restrict__ pe,
                  float* __restrict__ out)
{
    __shared__ float Xs[64][64];
    __shared__ float Ws[64][64];
    const int tid = threadIdx.x;
    const int tx = tid & 15, ty = tid >> 4;
    const int t0 = blockIdx.x * 64;
    const int c0 = blockIdx.y * 64;

    {
        const int r = tid >> 2, o4 = (tid & 3) * 16;
        const float* xp = X + (size_t)(t0 + r) * 64 + o4;
        const float* wp = W + (size_t)r * EMBED + c0 + o4;
        #pragma unroll
        for (int u = 0; u < 4; u++) {
            *(float4*)&Xs[r][o4 + 4*u] = *(const float4*)(xp + 4*u);
            *(float4*)&Ws[r][o4 + 4*u] = *(const float4*)(wp + 4*u);
        }
    }
    __syncthreads();

    float acc[4][4];
    #pragma unroll
    for (int i = 0; i < 4; i++)
        #pragma unroll
        for (int j = 0; j < 4; j++) acc[i][j] = 0.f;

    #pragma unroll 8
    for (int d = 0; d < 64; d++) {
        float4 wv = *(const float4*)&Ws[d][tx*4];
        #pragma unroll
        for (int i = 0; i < 4; i++) {
            float xr = Xs[ty*4 + i][d];
            acc[i][0] += xr * wv.x;
            acc[i][1] += xr * wv.y;
            acc[i][2] += xr * wv.z;
            acc[i][3] += xr * wv.w;
        }
    }

    float4 bv = *(const float4*)(bias + c0 + tx*4);
    #pragma unroll
    for (int i = 0; i < 4; i++) {
        int t = t0 + ty*4 + i;
        int s = t & (SEQ - 1);
        float4 pv = *(const float4*)(pe + (size_t)s*EMBED + c0 + tx*4);
        float4 r;
        r.x = acc[i][0] + bv.x + pv.x;
        r.y = acc[i][1] + bv.y + pv.y;
        r.z = acc[i][2] + bv.z + pv.z;
        r.w = acc[i][3] + bv.w + pv.w;
        *(float4*)(out + (size_t)t*EMBED + c0 + tx*4) = r;
    }
}

// ---------------------------------------------------------------------------
// QKV per-head 64x64 projections, writes [B,H,S,D] fp32
// ---------------------------------------------------------------------------
__global__ __launch_bounds__(256)
void qkv_kernel(const float* __restrict__ H,
                const float* __restrict__ Wq, const float* __restrict__ Wk,
                const float* __restrict__ Wv,
                float* __restrict__ Q, float* __restrict__ K, float* __restrict__ V)
{
    __shared__ float Xs[64][64];
    __shared__ float Ws[64][64];
    const int tid = threadIdx.x;
    const int tx = tid & 15, ty = tid >> 4;
    const int t0 = blockIdx.x * 64;
    const int hh = blockIdx.y;

    const int r = tid >> 2, o4 = (tid & 3) * 16;
    {
        const float* hp = H + (size_t)(t0 + r) * EMBED + hh*HDIM + o4;
        #pragma unroll
        for (int u = 0; u < 4; u++)
            *(float4*)&Xs[r][o4 + 4*u] = *(const float4*)(hp + 4*u);
    }

    const float* Wlist[3] = {Wq, Wk, Wv};
    float*       Olist[3] = {Q, K, V};

    for (int m = 0; m < 3; m++) {
        __syncthreads();
        {
            const float* wp = Wlist[m] + (size_t)r * 64 + o4;
            #pragma unroll
            for (int u = 0; u < 4; u++)
                *(float4*)&Ws[r][o4 + 4*u] = *(const float4*)(wp + 4*u);
        }
        __syncthreads();

        float acc[4][4];
        #pragma unroll
        for (int i = 0; i < 4; i++)
            #pragma unroll
            for (int j = 0; j < 4; j++) acc[i][j] = 0.f;

        #pragma unroll 8
        for (int d = 0; d < 64; d++) {
            float4 wv = *(const float4*)&Ws[d][tx*4];
            #pragma unroll
            for (int i = 0; i < 4; i++) {
                float xr = Xs[ty*4 + i][d];
                acc[i][0] += xr * wv.x;
                acc[i][1] += xr * wv.y;
                acc[i][2] += xr * wv.z;
                acc[i][3] += xr * wv.w;
            }
        }

        #pragma unroll
        for (int i = 0; i < 4; i++) {
            int t = t0 + ty*4 + i;
            int n = t >> 11;
            int s = t & (SEQ - 1);
            float* op = Olist[m] + ((size_t)(n*HEADS + hh)*SEQ + s)*HDIM + tx*4;
            *(float4*)op = make_float4(acc[i][0], acc[i][1], acc[i][2], acc[i][3]);
        }
    }
}

// ---------------------------------------------------------------------------
// Flash attention (all-ones mask), fp32 SIMT; writes fp16 output for GEMM A.
// ---------------------------------------------------------------------------
__global__ __launch_bounds__(256)
void attn_kernel(const float* __restrict__ Q, const float* __restrict__ K,
                 const float* __restrict__ V, __half* __restrict__ O)
{
    __shared__ float Qs[64][64];
    __shared__ float Ks[64][64];
    __shared__ float Vs[64][64];

    const int tid = threadIdx.x;
    const int tx = tid & 15, ty = tid >> 4;
    const int qt = blockIdx.x, bh = blockIdx.y;
    const int lr = tid >> 2;
    const int lc = (tid & 3) * 16;

    {
        const float* p = Q + ((size_t)bh * SEQ + qt*64) * HDIM + (size_t)lr*HDIM + lc;
        #pragma unroll
        for (int u = 0; u < 4; u++) {
            float4 v = *(const float4*)(p + 4*u);
            Qs[lc + 4*u + 0][lr] = v.x;
            Qs[lc + 4*u + 1][lr] = v.y;
            Qs[lc + 4*u + 2][lr] = v.z;
            Qs[lc + 4*u + 3][lr] = v.w;
        }
    }

    float m[4], l[4], o[4][4];
    #pragma unroll
    for (int i = 0; i < 4; i++) {
        m[i] = -3.0e38f; l[i] = 0.f;
        #pragma unroll
        for (int j = 0; j < 4; j++) o[i][j] = 0.f;
    }

    for (int kt = 0; kt < SEQ/64; kt++) {
        __syncthreads();
        {
            const float* pk = K + ((size_t)bh*SEQ + kt*64)*HDIM + (size_t)lr*HDIM + lc;
            const float* pv = V + ((size_t)bh*SEQ + kt*64)*HDIM + (size_t)lr*HDIM + lc;
            #pragma unroll
            for (int u = 0; u < 4; u++) {
                float4 kv = *(const float4*)(pk + 4*u);
                Ks[lc + 4*u + 0][lr] = kv.x;
                Ks[lc + 4*u + 1][lr] = kv.y;
                Ks[lc + 4*u + 2][lr] = kv.z;
                Ks[lc + 4*u + 3][lr] = kv.w;
                *(float4*)&Vs[lr][lc + 4*u] = *(const float4*)(pv + 4*u);
            }
        }
        __syncthreads();

        float s[4][4];
        #pragma unroll
        for (int i = 0; i < 4; i++)
            #pragma unroll
            for (int j = 0; j < 4; j++) s[i][j] = 0.f;

        #pragma unroll 8
        for (int d = 0; d < 64; d++) {
            float4 qv = *(const float4*)&Qs[d][ty*4];
            float4 kv = *(const float4*)&Ks[d][tx*4];
            s[0][0] += qv.x*kv.x; s[0][1] += qv.x*kv.y; s[0][2] += qv.x*kv.z; s[0][3] += qv.x*kv.w;
            s[1][0] += qv.y*kv.x; s[1][1] += qv.y*kv.y; s[1][2] += qv.y*kv.z; s[1][3] += qv.y*kv.w;
            s[2][0] += qv.z*kv.x; s[2][1] += qv.z*kv.y; s[2][2] += qv.z*kv.z; s[2][3] += qv.z*kv.w;
            s[3][0] += qv.w*kv.x; s[3][1] += qv.w*kv.y; s[3][2] += qv.w*kv.z; s[3][3] += qv.w*kv.w;
        }

        const float SCALE = 0.03125f;
        #pragma unroll
        for (int i = 0; i < 4; i++) {
            #pragma unroll
            for (int j = 0; j < 4; j++) s[i][j] *= SCALE;
            float rm = fmaxf(fmaxf(s[i][0], s[i][1]), fmaxf(s[i][2], s[i][3]));
            rm = fmaxf(rm, __shfl_xor_sync(0xffffffffu, rm, 8));
            rm = fmaxf(rm, __shfl_xor_sync(0xffffffffu, rm, 4));
            rm = fmaxf(rm, __shfl_xor_sync(0xffffffffu, rm, 2));
            rm = fmaxf(rm, __shfl_xor_sync(0xffffffffu, rm, 1));
            float nm  = fmaxf(m[i], rm);
            float fac = __expf(m[i] - nm);
            float rs = 0.f;
            #pragma unroll
            for (int j = 0; j < 4; j++) { s[i][j] = __expf(s[i][j] - nm); rs += s[i][j]; }
            rs += __shfl_xor_sync(0xffffffffu, rs, 8);
            rs += __shfl_xor_sync(0xffffffffu, rs, 4);
            rs += __shfl_xor_sync(0xffffffffu, rs, 2);
            rs += __shfl_xor_sync(0xffffffffu, rs, 1);
            l[i] = l[i]*fac + rs;
            m[i] = nm;
            #pragma unroll
            for (int j = 0; j < 4; j++) o[i][j] *= fac;
        }

        __syncthreads();
        float (*Ps)[64] = Ks;
        #pragma unroll
        for (int i = 0; i < 4; i++)
            #pragma unroll
            for (int j = 0; j < 4; j++) Ps[ty*4 + i][tx*4 + j] = s[i][j];
        __syncthreads();

        #pragma unroll 8
        for (int k = 0; k < 64; k++) {
            float4 vv = *(const float4*)&Vs[k][tx*4];
            #pragma unroll
            for (int i = 0; i < 4; i++) {
                float pk = Ps[ty*4 + i][k];
                o[i][0] += pk*vv.x;
                o[i][1] += pk*vv.y;
                o[i][2] += pk*vv.z;
                o[i][3] += pk*vv.w;
            }
        }
    }

    const int n = bh >> 4, hh = bh & 15;
    #pragma unroll
    for (int i = 0; i < 4; i++) {
        float inv = 1.f / l[i];
        int t = n*SEQ + qt*64 + ty*4 + i;
        __half* op = O + (size_t)t*EMBED + hh*HDIM + tx*4;
        uint2 hv;
        hv.x = pack_h2(o[i][0]*inv, o[i][1]*inv);
        hv.y = pack_h2(o[i][2]*inv, o[i][3]*inv);
        *(uint2*)op = hv;
    }
}

// ---------------------------------------------------------------------------
// Fused residual + LayerNorm; optionally emits an fp16 copy (for GEMM A)
// ---------------------------------------------------------------------------
template<int EMIT_H>
__global__ __launch_bounds__(256)
void ln_kernel(const float* __restrict__ A, const float* __restrict__ R,
               const float* __restrict__ gma, const float* __restrict__ bta,
               float* __restrict__ out, __half* __restrict__ outh)
{
    __shared__ float s1[8], s2[8];
    const int t = blockIdx.x, tid = threadIdx.x;
    const size_t base = (size_t)t * EMBED + tid * 4;

    float4 a = *(const float4*)(A + base);
    float4 r = *(const float4*)(R + base);
    float v0 = a.x + r.x, v1 = a.y + r.y, v2 = a.z + r.z, v3 = a.w + r.w;
    float sum = v0 + v1 + v2 + v3;
    float sq  = v0*v0 + v1*v1 + v2*v2 + v3*v3;

    #pragma unroll
    for (int off = 16; off > 0; off >>= 1) {
        sum += __shfl_xor_sync(0xffffffffu, sum, off);
        sq  += __shfl_xor_sync(0xffffffffu, sq,  off);
    }
    if ((tid & 31) == 0) { s1[tid >> 5] = sum; s2[tid >> 5] = sq; }
    __syncthreads();
    if (tid < 32) {
        float ss = (tid < 8) ? s1[tid] : 0.f;
        float qq = (tid < 8) ? s2[tid] : 0.f;
        #pragma unroll
        for (int off = 4; off > 0; off >>= 1) {
            ss += __shfl_xor_sync(0xffffffffu, ss, off);
            qq += __shfl_xor_sync(0xffffffffu, qq, off);
        }
        if (tid == 0) { s1[0] = ss; s2[0] = qq; }
    }
    __syncthreads();

    const float inv = 1.f / (float)EMBED;
    float mu  = s1[0] * inv;
    float var = s2[0] * inv - mu*mu;
    float rstd = rsqrtf(var + 1e-5f);

    float4 g = *(const float4*)(gma + tid*4);
    float4 b = *(const float4*)(bta + tid*4);
    float4 o;
    o.x = (v0 - mu)*rstd*g.x + b.x;
    o.y = (v1 - mu)*rstd*g.y + b.y;
    o.z = (v2 - mu)*rstd*g.z + b.z;
    o.w = (v3 - mu)*rstd*g.w + b.w;
    *(float4*)(out + base) = o;
    if (EMIT_H) {
        uint2 hv;
        hv.x = pack_h2(o.x, o.y);
        hv.y = pack_h2(o.z, o.w);
        *(uint2*)(outh + base) = hv;
    }
}

// ---------------------------------------------------------------------------
extern "C" void kernel_launch(void* const* d_in, const int* in_sizes, int n_in,
                              void* d_out, int out_size)
{
    const float* x       = (const float*)d_in[0];
    // d_in[1] = mask: all-true -> no-op
    const float* embed_W = (const float*)d_in[2];
    const float* embed_b = (const float*)d_in[3];
    const float* pe      = (const float*)d_in[4];
    const float* Wq      = (const float*)d_in[5];
    const float* Wk      = (const float*)d_in[6];
    const float* Wv      = (const float*)d_in[7];
    const float* Wo      = (const float*)d_in[8];
    const float* bo      = (const float*)d_in[9];
    const float* ln1_g   = (const float*)d_in[10];
    const float* ln1_b   = (const float*)d_in[11];
    const float* W1      = (const float*)d_in[12];
    const float* b1      = (const float*)d_in[13];
    const float* W2      = (const float*)d_in[14];
    const float* b2      = (const float*)d_in[15];
    const float* ln2_g   = (const float*)d_in[16];
    const float* ln2_b   = (const float*)d_in[17];
    float* h = (float*)d_out;

    float  *q, *k, *v, *t1, *x1, *t2;
    __half *oh, *x1h, *ffh, *woT, *w1T, *w2T;
    cudaGetSymbolAddress((void**)&q,   g_q);
    cudaGetSymbolAddress((void**)&k,   g_k);
    cudaGetSymbolAddress((void**)&v,   g_v);
    cudaGetSymbolAddress((void**)&t1,  g_t1);
    cudaGetSymbolAddress((void**)&x1,  g_x1);
    cudaGetSymbolAddress((void**)&t2,  g_t2);
    cudaGetSymbolAddress((void**)&oh,  g_oh);
    cudaGetSymbolAddress((void**)&x1h, g_x1h);
    cudaGetSymbolAddress((void**)&ffh, g_ffh);
    cudaGetSymbolAddress((void**)&woT, g_woT);
    cudaGetSymbolAddress((void**)&w1T, g_w1T);
    cudaGetSymbolAddress((void**)&w2T, g_w2T);

    cudaFuncSetAttribute(gemm_hmma<0,0>, cudaFuncAttributeMaxDynamicSharedMemorySize, GEMM_DSMEM);
    cudaFuncSetAttribute(gemm_hmma<1,1>, cudaFuncAttributeMaxDynamicSharedMemorySize, GEMM_DSMEM);

    // weight transposes -> half, k-major BT[n][k]
    transpose_h<<<dim3(EMBED/32, EMBED/32, 3), dim3(32,8)>>>(Wo, woT, EMBED, EMBED);
    transpose_h<<<dim3(FFN/32,   EMBED/32, 3), dim3(32,8)>>>(W1, w1T, EMBED, FFN);
    transpose_h<<<dim3(EMBED/32, FFN/32,   3), dim3(32,8)>>>(W2, w2T, FFN, EMBED);

    embed_kernel<<<dim3(TOK/64, EMBED/64), 256>>>(x, embed_W, embed_b, pe, h);

    for (int l = 0; l < 3; l++) {
        qkv_kernel<<<dim3(TOK/64, HEADS), 256>>>(
            h, Wq + l*HDIM*HDIM, Wk + l*HDIM*HDIM, Wv + l*HDIM*HDIM, q, k, v);

        attn_kernel<<<dim3(SEQ/64, BATCH*HEADS), 256>>>(q, k, v, oh);

        gemm_hmma<0,0><<<dim3(EMBED/128, TOK/128), 256, GEMM_DSMEM>>>(
            oh, woT + (size_t)l*EMBED*EMBED, bo + l*EMBED, t1, TOK, EMBED, EMBED);

        ln_kernel<1><<<TOK, 256>>>(t1, h, ln1_g + l*EMBED, ln1_b + l*EMBED, x1, x1h);

        gemm_hmma<1,1><<<dim3(FFN/128, TOK/128), 256, GEMM_DSMEM>>>(
            x1h, w1T + (size_t)l*EMBED*FFN, b1 + l*FFN, ffh, TOK, FFN, EMBED);

        gemm_hmma<0,0><<<dim3(EMBED/128, TOK/128), 256, GEMM_DSMEM>>>(
            ffh, w2T + (size_t)l*FFN*EMBED, b2 + l*EMBED, t2, TOK, EMBED, FFN);

        ln_kernel<0><<<TOK, 256>>>(t2, x1, ln2_g + l*EMBED, ln2_b + l*EMBED, h, (__half*)0);
    }
}

// round 12
// speedup vs baseline: 5.2632x; 2.3933x over previous
#include <cuda_runtime.h>
#include <cuda_fp16.h>
#include <math.h>
#include <stdint.h>

#define SEQ   2048
#define BATCH 2
#define EMBED 1024
#define HEADS 16
#define HDIM  64
#define FFN   4096
#define TOK   (BATCH*SEQ)   /* 4096 tokens */

// ---------------- scratch (device globals; no allocations allowed) ----------
static __device__ __half g_qh [TOK*EMBED];            // Q (pre-scaled 1/32) [B,H,S,D]
static __device__ __half g_kh [TOK*EMBED];            // K [B,H,S,D]
static __device__ __half g_vh [TOK*EMBED];            // V [B,H,S,D]
static __device__ float  g_t1 [TOK*EMBED];
static __device__ float  g_x1 [TOK*EMBED];
static __device__ float  g_t2 [TOK*EMBED];
static __device__ __half g_oh [TOK*EMBED];            // attn out (GEMM A)
static __device__ __half g_x1h[TOK*EMBED];            // ln1 out (GEMM A)
static __device__ __half g_ffh[(size_t)TOK*FFN];      // relu(ffn1) (GEMM A)
static __device__ __half g_woT[3*EMBED*EMBED];        // half, k-major BT[n][k]
static __device__ __half g_w1T[(size_t)3*EMBED*FFN];
static __device__ __half g_w2T[(size_t)3*FFN*EMBED];

// ---------------------------------------------------------------------------
// helpers
// ---------------------------------------------------------------------------
__device__ __forceinline__ uint32_t smem_u32(const void* p) {
    uint32_t a;
    asm("{ .reg .u64 t; cvta.to.shared.u64 t, %1; cvt.u32.u64 %0, t; }"
        : "=r"(a) : "l"(p));
    return a;
}
__device__ __forceinline__ void ldsm_x4(unsigned* r, uint32_t addr) {
    asm volatile("ldmatrix.sync.aligned.m8n8.x4.shared.b16 {%0,%1,%2,%3}, [%4];"
                 : "=r"(r[0]), "=r"(r[1]), "=r"(r[2]), "=r"(r[3]) : "r"(addr));
}
__device__ __forceinline__ void ldsm_x4_t(unsigned* r, uint32_t addr) {
    asm volatile("ldmatrix.sync.aligned.m8n8.x4.trans.shared.b16 {%0,%1,%2,%3}, [%4];"
                 : "=r"(r[0]), "=r"(r[1]), "=r"(r[2]), "=r"(r[3]) : "r"(addr));
}
__device__ __forceinline__ void mma16816(float* c, const unsigned* a, const unsigned* b) {
    asm volatile(
        "mma.sync.aligned.m16n8k16.row.col.f32.f16.f16.f32 "
        "{%0,%1,%2,%3}, {%4,%5,%6,%7}, {%8,%9}, {%0,%1,%2,%3};"
        : "+f"(c[0]), "+f"(c[1]), "+f"(c[2]), "+f"(c[3])
        : "r"(a[0]), "r"(a[1]), "r"(a[2]), "r"(a[3]), "r"(b[0]), "r"(b[1]));
}
// pack two fp32 into f16x2: lo = x, hi = y
__device__ __forceinline__ uint32_t pack_h2(float x, float y) {
    uint32_t r;
    asm("cvt.rn.f16x2.f32 %0, %1, %2;" : "=r"(r) : "f"(y), "f"(x));
    return r;
}
#define CP_ASYNC16(dst, src) \
    asm volatile("cp.async.cg.shared.global [%0], [%1], 16;" :: "r"(dst), "l"(src) : "memory")
#define CP_COMMIT()  asm volatile("cp.async.commit_group;" ::: "memory")
#define CP_WAIT(n)   asm volatile("cp.async.wait_group %0;" :: "n"(n) : "memory")

// ---------------------------------------------------------------------------
// fp16 mma.sync GEMM (R9, proven): C = A(half) @ B (BT[n][k] half)
// ---------------------------------------------------------------------------
#define SSTR   56
#define STG_B  (128*SSTR*2)
#define GEMM_DSMEM (4*STG_B)

template<int RELU, int OUT_HALF>
__global__ __launch_bounds__(256, 2)
void gemm_hmma(const __half* __restrict__ A, const __half* __restrict__ BT,
               const float* __restrict__ bias, void* __restrict__ Cv,
               int M, int N, int K)
{
    extern __shared__ __align__(16) char dsm[];
    const int tid  = threadIdx.x;
    const int lane = tid & 31, warp = tid >> 5;
    const int m0w = (warp >> 2) * 64;
    const int n0w = (warp & 3) * 32;
    const int rowBase = blockIdx.y * 128;
    const int colBase = blockIdx.x * 128;

    const uint32_t sb = smem_u32(dsm);
    const uint32_t aS = sb;
    const uint32_t bS = sb + 2*STG_B;

    const int lr = tid >> 1, lo = (tid & 1) * 16;
    const __half* Ag = A  + (size_t)(rowBase + lr) * K + lo;
    const __half* Bg = BT + (size_t)(colBase + lr) * K + lo;
    const uint32_t stOff = lr*(SSTR*2) + lo*2;

    float acc[4][4][4];
    #pragma unroll
    for (int mt = 0; mt < 4; mt++)
        #pragma unroll
        for (int nt = 0; nt < 4; nt++)
            #pragma unroll
            for (int r = 0; r < 4; r++) acc[mt][nt][r] = 0.f;

    #define ISSUE(c, stg)                                   \
    {                                                       \
        const __half* ag = Ag + (size_t)(c)*32;             \
        const __half* bg = Bg + (size_t)(c)*32;             \
        uint32_t ad = aS + (stg)*STG_B + stOff;             \
        uint32_t bd = bS + (stg)*STG_B + stOff;             \
        CP_ASYNC16(ad,      ag);                            \
        CP_ASYNC16(ad + 16, ag + 8);                        \
        CP_ASYNC16(bd,      bg);                            \
        CP_ASYNC16(bd + 16, bg + 8);                        \
        CP_COMMIT();                                        \
    }

    ISSUE(0, 0);

    const uint32_t aRow  = m0w + (lane & 15);
    const uint32_t aColB = ((lane >> 4) * 8) * 2;
    const uint32_t bRowB = (n0w + (lane >> 2)) * (SSTR*2);
    const uint32_t bColB = (lane & 3) * 4;

    const int NC = K >> 5;
    for (int c = 0; c < NC; c++) {
        const int cur = c & 1;
        if (c + 1 < NC) { ISSUE(c + 1, cur ^ 1); CP_WAIT(1); }
        else            { CP_WAIT(0); }
        __syncthreads();

        const uint32_t aSt = aS + cur*STG_B;
        const char*    bPt = dsm + 2*STG_B + cur*STG_B + bRowB + bColB;
        #pragma unroll
        for (int s = 0; s < 2; s++) {
            const uint32_t k0B = s * 32;
            unsigned af[4][4], bf[4][2];
            #pragma unroll
            for (int mt = 0; mt < 4; mt++)
                ldsm_x4(af[mt], aSt + (aRow + mt*16)*(SSTR*2) + k0B + aColB);
            #pragma unroll
            for (int nt = 0; nt < 4; nt++) {
                const char* nb = bPt + nt*8*(SSTR*2) + k0B;
                bf[nt][0] = *(const unsigned*)(nb);
                bf[nt][1] = *(const unsigned*)(nb + 16);
            }
            #pragma unroll
            for (int mt = 0; mt < 4; mt++)
                #pragma unroll
                for (int nt = 0; nt < 4; nt++)
                    mma16816(acc[mt][nt], af[mt], bf[nt]);
        }
        __syncthreads();
    }
    #undef ISSUE

    const int er = lane >> 2, ec = (lane & 3) * 2;
    #pragma unroll
    for (int mt = 0; mt < 4; mt++) {
        const int row = rowBase + m0w + mt*16 + er;
        #pragma unroll
        for (int nt = 0; nt < 4; nt++) {
            const int col = colBase + n0w + nt*8 + ec;
            float2 bv = *(const float2*)(bias + col);
            float v0 = acc[mt][nt][0] + bv.x;
            float v1 = acc[mt][nt][1] + bv.y;
            float v2 = acc[mt][nt][2] + bv.x;
            float v3 = acc[mt][nt][3] + bv.y;
            if (RELU) {
                v0 = fmaxf(v0, 0.f); v1 = fmaxf(v1, 0.f);
                v2 = fmaxf(v2, 0.f); v3 = fmaxf(v3, 0.f);
            }
            if (OUT_HALF) {
                __half* C = (__half*)Cv;
                *(unsigned*)&C[(size_t)row*N + col]     = pack_h2(v0, v1);
                *(unsigned*)&C[(size_t)(row+8)*N + col] = pack_h2(v2, v3);
            } else {
                float* C = (float*)Cv;
                *(float2*)&C[(size_t)row*N + col]     = make_float2(v0, v1);
                *(float2*)&C[(size_t)(row+8)*N + col] = make_float2(v2, v3);
            }
        }
    }
}

// ---------------------------------------------------------------------------
// fp16 mma.sync flash attention. Q pre-scaled by 1/32. All-ones mask.
// 128 threads = 4 warps x m16 q-rows = 64 q-rows/CTA; K-tile 64; D=64.
// smem: Q[64][72]h + K[2][64][72]h + V[2][64][72]h = 46080 B (static).
// ---------------------------------------------------------------------------
#define APAD 72
#define AROWB (APAD*2)      /* 144 B row stride */

__global__ __launch_bounds__(128)
void attn_mma(const __half* __restrict__ Q, const __half* __restrict__ K,
              const __half* __restrict__ V, __half* __restrict__ O)
{
    __shared__ __align__(16) __half QS[64][APAD];
    __shared__ __align__(16) __half KS[2][64][APAD];
    __shared__ __align__(16) __half VS[2][64][APAD];

    const int tid  = threadIdx.x;
    const int lane = tid & 31, warp = tid >> 5;
    const int qt = blockIdx.x, bh = blockIdx.y;

    // loader: 2 threads/row, 4 x 16B each (64 halfs/row)
    const int lr = tid >> 1;                   // row 0..63
    const int lc = (tid & 1) * 32;             // half offset 0/32
    const size_t gQ = ((size_t)bh*SEQ + qt*64 + lr) * HDIM + lc;
    const uint32_t qDst = smem_u32(&QS[lr][lc]);
    const uint32_t kDst0 = smem_u32(&KS[0][lr][lc]);
    const uint32_t vDst0 = smem_u32(&VS[0][lr][lc]);
    const uint32_t stgB  = smem_u32(&KS[1][0][0]) - smem_u32(&KS[0][0][0]);

    #define LD4(dst, src)                       \
        CP_ASYNC16((dst),      (src));          \
        CP_ASYNC16((dst)+16,   (src)+8);        \
        CP_ASYNC16((dst)+32,   (src)+16);       \
        CP_ASYNC16((dst)+48,   (src)+24);

    // group 0: Q + K0 + V0
    {
        const __half* kg = K + ((size_t)bh*SEQ + lr)*HDIM + lc;
        const __half* vg = V + ((size_t)bh*SEQ + lr)*HDIM + lc;
        LD4(qDst, Q + gQ);
        LD4(kDst0, kg);
        LD4(vDst0, vg);
        CP_COMMIT();
    }

    float sacc[8][4], oacc[8][4];
    float mr0 = -1e30f, mr1 = -1e30f, lr0 = 0.f, lr1 = 0.f;
    #pragma unroll
    for (int nt = 0; nt < 8; nt++)
        #pragma unroll
        for (int r = 0; r < 4; r++) oacc[nt][r] = 0.f;

    unsigned qf[4][4];
    const uint32_t aRow  = warp*16 + (lane & 15);
    const uint32_t aColB = (lane >> 4) * 16;
    const int bRow = lane >> 2;
    const int bColB = (lane & 3) * 4;

    const int NT = SEQ / 64;
    for (int kt = 0; kt < NT; kt++) {
        const int cur = kt & 1;
        if (kt + 1 < NT) {
            const __half* kg = K + ((size_t)bh*SEQ + (kt+1)*64 + lr)*HDIM + lc;
            const __half* vg = V + ((size_t)bh*SEQ + (kt+1)*64 + lr)*HDIM + lc;
            LD4(kDst0 + (cur^1)*stgB, kg);
            LD4(vDst0 + (cur^1)*stgB, vg);
            CP_COMMIT();
            CP_WAIT(1);
        } else {
            CP_WAIT(0);
        }
        __syncthreads();

        if (kt == 0) {
            const uint32_t qB = smem_u32(&QS[0][0]);
            #pragma unroll
            for (int kc = 0; kc < 4; kc++)
                ldsm_x4(qf[kc], qB + aRow*AROWB + kc*32 + aColB);
        }

        // ---- S = Q K^T (per warp: m16 x n64) ----
        #pragma unroll
        for (int nt = 0; nt < 8; nt++) {
            #pragma unroll
            for (int r = 0; r < 4; r++) sacc[nt][r] = 0.f;
            const char* nb = (const char*)&KS[cur][nt*8 + bRow][0] + bColB;
            #pragma unroll
            for (int kc = 0; kc < 4; kc++) {
                unsigned b[2];
                b[0] = *(const unsigned*)(nb + kc*32);
                b[1] = *(const unsigned*)(nb + kc*32 + 16);
                mma16816(sacc[nt], qf[kc], b);
            }
        }

        // ---- online softmax on fragments ----
        float mx0 = -1e30f, mx1 = -1e30f;
        #pragma unroll
        for (int nt = 0; nt < 8; nt++) {
            mx0 = fmaxf(mx0, fmaxf(sacc[nt][0], sacc[nt][1]));
            mx1 = fmaxf(mx1, fmaxf(sacc[nt][2], sacc[nt][3]));
        }
        mx0 = fmaxf(mx0, __shfl_xor_sync(0xffffffffu, mx0, 1));
        mx0 = fmaxf(mx0, __shfl_xor_sync(0xffffffffu, mx0, 2));
        mx1 = fmaxf(mx1, __shfl_xor_sync(0xffffffffu, mx1, 1));
        mx1 = fmaxf(mx1, __shfl_xor_sync(0xffffffffu, mx1, 2));
        const float nm0 = fmaxf(mr0, mx0), nm1 = fmaxf(mr1, mx1);
        const float fac0 = __expf(mr0 - nm0), fac1 = __expf(mr1 - nm1);
        float sum0 = 0.f, sum1 = 0.f;
        #pragma unroll
        for (int nt = 0; nt < 8; nt++) {
            sacc[nt][0] = __expf(sacc[nt][0] - nm0);
            sacc[nt][1] = __expf(sacc[nt][1] - nm0);
            sacc[nt][2] = __expf(sacc[nt][2] - nm1);
            sacc[nt][3] = __expf(sacc[nt][3] - nm1);
            sum0 += sacc[nt][0] + sacc[nt][1];
            sum1 += sacc[nt][2] + sacc[nt][3];
        }
        sum0 += __shfl_xor_sync(0xffffffffu, sum0, 1);
        sum0 += __shfl_xor_sync(0xffffffffu, sum0, 2);
        sum1 += __shfl_xor_sync(0xffffffffu, sum1, 1);
        sum1 += __shfl_xor_sync(0xffffffffu, sum1, 2);
        lr0 = lr0*fac0 + sum0;  mr0 = nm0;
        lr1 = lr1*fac1 + sum1;  mr1 = nm1;
        #pragma unroll
        for (int nt = 0; nt < 8; nt++) {
            oacc[nt][0] *= fac0; oacc[nt][1] *= fac0;
            oacc[nt][2] *= fac1; oacc[nt][3] *= fac1;
        }

        // ---- pack P (C-frag -> A-frag, register-exact) ----
        unsigned pa[4][4];
        #pragma unroll
        for (int sc = 0; sc < 4; sc++) {
            pa[sc][0] = pack_h2(sacc[2*sc  ][0], sacc[2*sc  ][1]);
            pa[sc][1] = pack_h2(sacc[2*sc  ][2], sacc[2*sc  ][3]);
            pa[sc][2] = pack_h2(sacc[2*sc+1][0], sacc[2*sc+1][1]);
            pa[sc][3] = pack_h2(sacc[2*sc+1][2], sacc[2*sc+1][3]);
        }

        // ---- O += P V  (V B-frags via ldmatrix.trans) ----
        const uint32_t vB = smem_u32(&VS[cur][0][0]);
        const int g = lane >> 3, r8 = lane & 7;
        #pragma unroll
        for (int sc = 0; sc < 4; sc++) {
            #pragma unroll
            for (int dp = 0; dp < 4; dp++) {
                // mat0 (lanes 0-7):  V[sc16+r][dp16+0..8)
                // mat1 (lanes 8-15): V[sc16+8+r][dp16+0..8)
                // mat2 (lanes16-23): V[sc16+r][dp16+8..16)
                // mat3 (lanes24-31): V[sc16+8+r][dp16+8..16)
                const uint32_t addr = vB
                    + (sc*16 + ((g & 1) ? 8 : 0) + r8)*AROWB
                    + (dp*16 + ((g >> 1) ? 8 : 0))*2;
                unsigned vf[4];
                ldsm_x4_t(vf, addr);
                mma16816(oacc[2*dp  ], pa[sc], vf);       // vf[0],vf[1]
                mma16816(oacc[2*dp+1], pa[sc], vf + 2);   // vf[2],vf[3]
            }
        }
        __syncthreads();
    }
    #undef LD4

    // ---- epilogue: O / l, write half to [token][EMBED] ----
    const int n = bh >> 4, hh = bh & 15;
    const float i0 = 1.f / lr0, i1 = 1.f / lr1;
    const int row0 = qt*64 + warp*16 + (lane >> 2);
    const int t0 = n*SEQ + row0, t1 = t0 + 8;
    #pragma unroll
    for (int dt = 0; dt < 8; dt++) {
        const int col = hh*HDIM + dt*8 + (lane & 3)*2;
        *(unsigned*)&O[(size_t)t0*EMBED + col] = pack_h2(oacc[dt][0]*i0, oacc[dt][1]*i0);
        *(unsigned*)&O[(size_t)t1*EMBED + col] = pack_h2(oacc[dt][2]*i1, oacc[dt][3]*i1);
    }
}

// ---------------------------------------------------------------------------
// 32x32 tiled transpose + fp16 convert
// ---------------------------------------------------------------------------
__global__ __launch_bounds__(256)
void transpose_h(const float* __restrict__ src, __half* __restrict__ dst, int R, int C)
{
    __shared__ float t[32][33];
    const float* s = src + (size_t)blockIdx.z * R * C;
    __half*      d = dst + (size_t)blockIdx.z * R * C;
    int x  = blockIdx.x*32 + threadIdx.x;
    int y0 = blockIdx.y*32;
    #pragma unroll
    for (int j = 0; j < 4; j++)
        t[threadIdx.y + 8*j][threadIdx.x] = s[(size_t)(y0 + threadIdx.y + 8*j)*C + x];
    __syncthreads();
    int x2 = blockIdx.y*32 + threadIdx.x;
    int y2 = blockIdx.x*32;
    #pragma unroll
    for (int j = 0; j < 4; j++)
        d[(size_t)(y2 + threadIdx.y + 8*j)*R + x2] = __float2half(t[threadIdx.x][threadIdx.y + 8*j]);
}

// ---------------------------------------------------------------------------
// Embed
// ---------------------------------------------------------------------------
__global__ __launch_bounds__(256)
void embed_kernel(const float* __restrict__ X, const float* __restrict__ W,
                  const float* __restrict__ bias, const float* __restrict__ pe,
                  float* __restrict__ out)
{
    __shared__ float Xs[64][64];
    __shared__ float Ws[64][64];
    const int tid = threadIdx.x;
    const int tx = tid & 15, ty = tid >> 4;
    const int t0 = blockIdx.x * 64;
    const int c0 = blockIdx.y * 64;

    {
        const int r = tid >> 2, o4 = (tid & 3) * 16;
        const float* xp = X + (size_t)(t0 + r) * 64 + o4;
        const float* wp = W + (size_t)r * EMBED + c0 + o4;
        #pragma unroll
        for (int u = 0; u < 4; u++) {
            *(float4*)&Xs[r][o4 + 4*u] = *(const float4*)(xp + 4*u);
            *(float4*)&Ws[r][o4 + 4*u] = *(const float4*)(wp + 4*u);
        }
    }
    __syncthreads();

    float acc[4][4];
    #pragma unroll
    for (int i = 0; i < 4; i++)
        #pragma unroll
        for (int j = 0; j < 4; j++) acc[i][j] = 0.f;

    #pragma unroll 8
    for (int d = 0; d < 64; d++) {
        float4 wv = *(const float4*)&Ws[d][tx*4];
        #pragma unroll
        for (int i = 0; i < 4; i++) {
            float xr = Xs[ty*4 + i][d];
            acc[i][0] += xr * wv.x;
            acc[i][1] += xr * wv.y;
            acc[i][2] += xr * wv.z;
            acc[i][3] += xr * wv.w;
        }
    }

    float4 bv = *(const float4*)(bias + c0 + tx*4);
    #pragma unroll
    for (int i = 0; i < 4; i++) {
        int t = t0 + ty*4 + i;
        int s = t & (SEQ - 1);
        float4 pv = *(const float4*)(pe + (size_t)s*EMBED + c0 + tx*4);
        float4 r;
        r.x = acc[i][0] + bv.x + pv.x;
        r.y = acc[i][1] + bv.y + pv.y;
        r.z = acc[i][2] + bv.z + pv.z;
        r.w = acc[i][3] + bv.w + pv.w;
        *(float4*)(out + (size_t)t*EMBED + c0 + tx*4) = r;
    }
}

// ---------------------------------------------------------------------------
// QKV per-head 64x64 projections -> half [B,H,S,D]; Q scaled by 1/32.
// ---------------------------------------------------------------------------
__global__ __launch_bounds__(256)
void qkv_kernel(const float* __restrict__ H,
                const float* __restrict__ Wq, const float* __restrict__ Wk,
                const float* __restrict__ Wv,
                __half* __restrict__ Q, __half* __restrict__ K, __half* __restrict__ V)
{
    __shared__ float Xs[64][64];
    __shared__ float Ws[64][64];
    const int tid = threadIdx.x;
    const int tx = tid & 15, ty = tid >> 4;
    const int t0 = blockIdx.x * 64;
    const int hh = blockIdx.y;

    const int r = tid >> 2, o4 = (tid & 3) * 16;
    {
        const float* hp = H + (size_t)(t0 + r) * EMBED + hh*HDIM + o4;
        #pragma unroll
        for (int u = 0; u < 4; u++)
            *(float4*)&Xs[r][o4 + 4*u] = *(const float4*)(hp + 4*u);
    }

    const float* Wlist[3] = {Wq, Wk, Wv};
    __half*      Olist[3] = {Q, K, V};

    for (int m = 0; m < 3; m++) {
        __syncthreads();
        {
            const float* wp = Wlist[m] + (size_t)r * 64 + o4;
            #pragma unroll
            for (int u = 0; u < 4; u++)
                *(float4*)&Ws[r][o4 + 4*u] = *(const float4*)(wp + 4*u);
        }
        __syncthreads();

        float acc[4][4];
        #pragma unroll
        for (int i = 0; i < 4; i++)
            #pragma unroll
            for (int j = 0; j < 4; j++) acc[i][j] = 0.f;

        #pragma unroll 8
        for (int d = 0; d < 64; d++) {
            float4 wv = *(const float4*)&Ws[d][tx*4];
            #pragma unroll
            for (int i = 0; i < 4; i++) {
                float xr = Xs[ty*4 + i][d];
                acc[i][0] += xr * wv.x;
                acc[i][1] += xr * wv.y;
                acc[i][2] += xr * wv.z;
                acc[i][3] += xr * wv.w;
            }
        }

        const float sc = (m == 0) ? 0.03125f : 1.0f;   // exact power of 2
        #pragma unroll
        for (int i = 0; i < 4; i++) {
            int t = t0 + ty*4 + i;
            int n = t >> 11;
            int s = t & (SEQ - 1);
            __half* op = Olist[m] + ((size_t)(n*HEADS + hh)*SEQ + s)*HDIM + tx*4;
            uint2 hv;
            hv.x = pack_h2(acc[i][0]*sc, acc[i][1]*sc);
            hv.y = pack_h2(acc[i][2]*sc, acc[i][3]*sc);
            *(uint2*)op = hv;
        }
    }
}

// ---------------------------------------------------------------------------
// Fused residual + LayerNorm (+ optional fp16 copy)
// ---------------------------------------------------------------------------
template<int EMIT_H>
__global__ __launch_bounds__(256)
void ln_kernel(const float* __restrict__ A, const float* __restrict__ R,
               const float* __restrict__ gma, const float* __restrict__ bta,
               float* __restrict__ out, __half* __restrict__ outh)
{
    __shared__ float s1[8], s2[8];
    const int t = blockIdx.x, tid = threadIdx.x;
    const size_t base = (size_t)t * EMBED + tid * 4;

    float4 a = *(const float4*)(A + base);
    float4 r = *(const float4*)(R + base);
    float v0 = a.x + r.x, v1 = a.y + r.y, v2 = a.z + r.z, v3 = a.w + r.w;
    float sum = v0 + v1 + v2 + v3;
    float sq  = v0*v0 + v1*v1 + v2*v2 + v3*v3;

    #pragma unroll
    for (int off = 16; off > 0; off >>= 1) {
        sum += __shfl_xor_sync(0xffffffffu, sum, off);
        sq  += __shfl_xor_sync(0xffffffffu, sq,  off);
    }
    if ((tid & 31) == 0) { s1[tid >> 5] = sum; s2[tid >> 5] = sq; }
    __syncthreads();
    if (tid < 32) {
        float ss = (tid < 8) ? s1[tid] : 0.f;
        float qq = (tid < 8) ? s2[tid] : 0.f;
        #pragma unroll
        for (int off = 4; off > 0; off >>= 1) {
            ss += __shfl_xor_sync(0xffffffffu, ss, off);
            qq += __shfl_xor_sync(0xffffffffu, qq, off);
        }
        if (tid == 0) { s1[0] = ss; s2[0] = qq; }
    }
    __syncthreads();

    const float inv = 1.f / (float)EMBED;
    float mu  = s1[0] * inv;
    float var = s2[0] * inv - mu*mu;
    float rstd = rsqrtf(var + 1e-5f);

    float4 g = *(const float4*)(gma + tid*4);
    float4 b = *(const float4*)(bta + tid*4);
    float4 o;
    o.x = (v0 - mu)*rstd*g.x + b.x;
    o.y = (v1 - mu)*rstd*g.y + b.y;
    o.z = (v2 - mu)*rstd*g.z + b.z;
    o.w = (v3 - mu)*rstd*g.w + b.w;
    *(float4*)(out + base) = o;
    if (EMIT_H) {
        uint2 hv;
        hv.x = pack_h2(o.x, o.y);
        hv.y = pack_h2(o.z, o.w);
        *(uint2*)(outh + base) = hv;
    }
}

// ---------------------------------------------------------------------------
extern "C" void kernel_launch(void* const* d_in, const int* in_sizes, int n_in,
                              void* d_out, int out_size)
{
    const float* x       = (const float*)d_in[0];
    // d_in[1] = mask: all-true -> no-op
    const float* embed_W = (const float*)d_in[2];
    const float* embed_b = (const float*)d_in[3];
    const float* pe      = (const float*)d_in[4];
    const float* Wq      = (const float*)d_in[5];
    const float* Wk      = (const float*)d_in[6];
    const float* Wv      = (const float*)d_in[7];
    const float* Wo      = (const float*)d_in[8];
    const float* bo      = (const float*)d_in[9];
    const float* ln1_g   = (const float*)d_in[10];
    const float* ln1_b   = (const float*)d_in[11];
    const float* W1      = (const float*)d_in[12];
    const float* b1      = (const float*)d_in[13];
    const float* W2      = (const float*)d_in[14];
    const float* b2      = (const float*)d_in[15];
    const float* ln2_g   = (const float*)d_in[16];
    const float* ln2_b   = (const float*)d_in[17];
    float* h = (float*)d_out;

    float  *t1, *x1, *t2;
    __half *qh, *kh, *vh, *oh, *x1h, *ffh, *woT, *w1T, *w2T;
    cudaGetSymbolAddress((void**)&qh,  g_qh);
    cudaGetSymbolAddress((void**)&kh,  g_kh);
    cudaGetSymbolAddress((void**)&vh,  g_vh);
    cudaGetSymbolAddress((void**)&t1,  g_t1);
    cudaGetSymbolAddress((void**)&x1,  g_x1);
    cudaGetSymbolAddress((void**)&t2,  g_t2);
    cudaGetSymbolAddress((void**)&oh,  g_oh);
    cudaGetSymbolAddress((void**)&x1h, g_x1h);
    cudaGetSymbolAddress((void**)&ffh, g_ffh);
    cudaGetSymbolAddress((void**)&woT, g_woT);
    cudaGetSymbolAddress((void**)&w1T, g_w1T);
    cudaGetSymbolAddress((void**)&w2T, g_w2T);

    cudaFuncSetAttribute(gemm_hmma<0,0>, cudaFuncAttributeMaxDynamicSharedMemorySize, GEMM_DSMEM);
    cudaFuncSetAttribute(gemm_hmma<1,1>, cudaFuncAttributeMaxDynamicSharedMemorySize, GEMM_DSMEM);

    transpose_h<<<dim3(EMBED/32, EMBED/32, 3), dim3(32,8)>>>(Wo, woT, EMBED, EMBED);
    transpose_h<<<dim3(FFN/32,   EMBED/32, 3), dim3(32,8)>>>(W1, w1T, EMBED, FFN);
    transpose_h<<<dim3(EMBED/32, FFN/32,   3), dim3(32,8)>>>(W2, w2T, FFN, EMBED);

    embed_kernel<<<dim3(TOK/64, EMBED/64), 256>>>(x, embed_W, embed_b, pe, h);

    for (int l = 0; l < 3; l++) {
        qkv_kernel<<<dim3(TOK/64, HEADS), 256>>>(
            h, Wq + l*HDIM*HDIM, Wk + l*HDIM*HDIM, Wv + l*HDIM*HDIM, qh, kh, vh);

        attn_mma<<<dim3(SEQ/64, BATCH*HEADS), 128>>>(qh, kh, vh, oh);

        gemm_hmma<0,0><<<dim3(EMBED/128, TOK/128), 256, GEMM_DSMEM>>>(
            oh, woT + (size_t)l*EMBED*EMBED, bo + l*EMBED, t1, TOK, EMBED, EMBED);

        ln_kernel<1><<<TOK, 256>>>(t1, h, ln1_g + l*EMBED, ln1_b + l*EMBED, x1, x1h);

        gemm_hmma<1,1><<<dim3(FFN/128, TOK/128), 256, GEMM_DSMEM>>>(
            x1h, w1T + (size_t)l*EMBED*FFN, b1 + l*FFN, ffh, TOK, FFN, EMBED);

        gemm_hmma<0,0><<<dim3(EMBED/128, TOK/128), 256, GEMM_DSMEM>>>(
            ffh, w2T + (size_t)l*FFN*EMBED, b2 + l*EMBED, t2, TOK, EMBED, FFN);

        ln_kernel<0><<<TOK, 256>>>(t2, x1, ln2_g + l*EMBED, ln2_b + l*EMBED, h, (__half*)0);
    }
}

// round 13
// speedup vs baseline: 5.5604x; 1.0565x over previous
#include <cuda_runtime.h>
#include <cuda_fp16.h>
#include <math.h>
#include <stdint.h>

#define SEQ   2048
#define BATCH 2
#define EMBED 1024
#define HEADS 16
#define HDIM  64
#define FFN   4096
#define TOK   (BATCH*SEQ)   /* 4096 tokens */

// ---------------- scratch (device globals; no allocations allowed) ----------
static __device__ __half g_hh [TOK*EMBED];            // half copy of h (QKV input)
static __device__ __half g_qh [TOK*EMBED];            // Q (pre-scaled 1/32) [B,H,S,D]
static __device__ __half g_kh [TOK*EMBED];            // K [B,H,S,D]
static __device__ __half g_vh [TOK*EMBED];            // V [B,H,S,D]
static __device__ float  g_t1 [TOK*EMBED];
static __device__ float  g_x1 [TOK*EMBED];
static __device__ float  g_t2 [TOK*EMBED];
static __device__ __half g_oh [TOK*EMBED];            // attn out (GEMM A)
static __device__ __half g_x1h[TOK*EMBED];            // ln1 out (GEMM A)
static __device__ __half g_ffh[(size_t)TOK*FFN];      // relu(ffn1) (GEMM A)
static __device__ __half g_woT[3*EMBED*EMBED];        // half, k-major BT[n][k]
static __device__ __half g_w1T[(size_t)3*EMBED*FFN];
static __device__ __half g_w2T[(size_t)3*FFN*EMBED];
static __device__ __half g_wqkvT[3*3*HDIM*HDIM];      // [layer][q/k/v][e][d] half

// ---------------------------------------------------------------------------
// helpers
// ---------------------------------------------------------------------------
__device__ __forceinline__ uint32_t smem_u32(const void* p) {
    uint32_t a;
    asm("{ .reg .u64 t; cvta.to.shared.u64 t, %1; cvt.u32.u64 %0, t; }"
        : "=r"(a) : "l"(p));
    return a;
}
__device__ __forceinline__ void ldsm_x4(unsigned* r, uint32_t addr) {
    asm volatile("ldmatrix.sync.aligned.m8n8.x4.shared.b16 {%0,%1,%2,%3}, [%4];"
                 : "=r"(r[0]), "=r"(r[1]), "=r"(r[2]), "=r"(r[3]) : "r"(addr));
}
__device__ __forceinline__ void ldsm_x4_t(unsigned* r, uint32_t addr) {
    asm volatile("ldmatrix.sync.aligned.m8n8.x4.trans.shared.b16 {%0,%1,%2,%3}, [%4];"
                 : "=r"(r[0]), "=r"(r[1]), "=r"(r[2]), "=r"(r[3]) : "r"(addr));
}
__device__ __forceinline__ void mma16816(float* c, const unsigned* a, const unsigned* b) {
    asm volatile(
        "mma.sync.aligned.m16n8k16.row.col.f32.f16.f16.f32 "
        "{%0,%1,%2,%3}, {%4,%5,%6,%7}, {%8,%9}, {%0,%1,%2,%3};"
        : "+f"(c[0]), "+f"(c[1]), "+f"(c[2]), "+f"(c[3])
        : "r"(a[0]), "r"(a[1]), "r"(a[2]), "r"(a[3]), "r"(b[0]), "r"(b[1]));
}
// pack two fp32 into f16x2: lo = x, hi = y
__device__ __forceinline__ uint32_t pack_h2(float x, float y) {
    uint32_t r;
    asm("cvt.rn.f16x2.f32 %0, %1, %2;" : "=r"(r) : "f"(y), "f"(x));
    return r;
}
#define CP_ASYNC16(dst, src) \
    asm volatile("cp.async.cg.shared.global [%0], [%1], 16;" :: "r"(dst), "l"(src) : "memory")
#define CP_COMMIT()  asm volatile("cp.async.commit_group;" ::: "memory")
#define CP_WAIT(n)   asm volatile("cp.async.wait_group %0;" :: "n"(n) : "memory")

// ---------------------------------------------------------------------------
// fp16 mma.sync GEMM, 3-stage cp.async pipeline.
// C(MxN) = A(MxK,row-major,half) @ B, BT[n][k] half; + bias (+ReLU).
// CTA 128x128, k-chunk 32; 8 warps (2m x 4n), warp tile 64x32.
// ---------------------------------------------------------------------------
#define SSTR   56
#define STG_B  (128*SSTR*2)          /* 14336 B per operand stage */
#define GEMM_DSMEM (6*STG_B)         /* 86016 B: 3 stages x 2 operands */

template<int RELU, int OUT_HALF>
__global__ __launch_bounds__(256, 2)
void gemm_hmma(const __half* __restrict__ A, const __half* __restrict__ BT,
               const float* __restrict__ bias, void* __restrict__ Cv,
               int M, int N, int K)
{
    extern __shared__ __align__(16) char dsm[];
    const int tid  = threadIdx.x;
    const int lane = tid & 31, warp = tid >> 5;
    const int m0w = (warp >> 2) * 64;
    const int n0w = (warp & 3) * 32;
    const int rowBase = blockIdx.y * 128;
    const int colBase = blockIdx.x * 128;

    const uint32_t sb = smem_u32(dsm);
    const uint32_t aS = sb;                 // A stages: +0, +STG_B, +2*STG_B
    const uint32_t bS = sb + 3*STG_B;       // B stages

    const int lr = tid >> 1, lo = (tid & 1) * 16;
    const __half* Ag = A  + (size_t)(rowBase + lr) * K + lo;
    const __half* Bg = BT + (size_t)(colBase + lr) * K + lo;
    const uint32_t stOff = lr*(SSTR*2) + lo*2;

    float acc[4][4][4];
    #pragma unroll
    for (int mt = 0; mt < 4; mt++)
        #pragma unroll
        for (int nt = 0; nt < 4; nt++)
            #pragma unroll
            for (int r = 0; r < 4; r++) acc[mt][nt][r] = 0.f;

    #define ISSUE(c, stg)                                   \
    {                                                       \
        const __half* ag = Ag + (size_t)(c)*32;             \
        const __half* bg = Bg + (size_t)(c)*32;             \
        uint32_t ad = aS + (stg)*STG_B + stOff;             \
        uint32_t bd = bS + (stg)*STG_B + stOff;             \
        CP_ASYNC16(ad,      ag);                            \
        CP_ASYNC16(ad + 16, ag + 8);                        \
        CP_ASYNC16(bd,      bg);                            \
        CP_ASYNC16(bd + 16, bg + 8);                        \
        CP_COMMIT();                                        \
    }

    const int NC = K >> 5;     // K >= 64 always here
    ISSUE(0, 0);
    ISSUE(1, 1);

    const uint32_t aRow  = m0w + (lane & 15);
    const uint32_t aColB = ((lane >> 4) * 8) * 2;
    const uint32_t bRowB = (n0w + (lane >> 2)) * (SSTR*2);
    const uint32_t bColB = (lane & 3) * 4;

    for (int c = 0; c < NC; c++) {
        if (c + 1 < NC) CP_WAIT(1); else CP_WAIT(0);
        __syncthreads();
        // safe: stage (c+2)%3 == stage (c-1)%3, whose readers finished before
        // this barrier; current compute reads stage c%3 (distinct mod 3).
        if (c + 2 < NC) { const int ns = (c + 2) % 3; ISSUE(c + 2, ns); }

        const int cur = c % 3;
        const uint32_t aSt = aS + cur*STG_B;
        const char*    bPt = dsm + 3*STG_B + cur*STG_B + bRowB + bColB;
        #pragma unroll
        for (int s = 0; s < 2; s++) {
            const uint32_t k0B = s * 32;
            unsigned af[4][4], bf[4][2];
            #pragma unroll
            for (int mt = 0; mt < 4; mt++)
                ldsm_x4(af[mt], aSt + (aRow + mt*16)*(SSTR*2) + k0B + aColB);
            #pragma unroll
            for (int nt = 0; nt < 4; nt++) {
                const char* nb = bPt + nt*8*(SSTR*2) + k0B;
                bf[nt][0] = *(const unsigned*)(nb);
                bf[nt][1] = *(const unsigned*)(nb + 16);
            }
            #pragma unroll
            for (int mt = 0; mt < 4; mt++)
                #pragma unroll
                for (int nt = 0; nt < 4; nt++)
                    mma16816(acc[mt][nt], af[mt], bf[nt]);
        }
    }
    #undef ISSUE

    const int er = lane >> 2, ec = (lane & 3) * 2;
    #pragma unroll
    for (int mt = 0; mt < 4; mt++) {
        const int row = rowBase + m0w + mt*16 + er;
        #pragma unroll
        for (int nt = 0; nt < 4; nt++) {
            const int col = colBase + n0w + nt*8 + ec;
            float2 bv = *(const float2*)(bias + col);
            float v0 = acc[mt][nt][0] + bv.x;
            float v1 = acc[mt][nt][1] + bv.y;
            float v2 = acc[mt][nt][2] + bv.x;
            float v3 = acc[mt][nt][3] + bv.y;
            if (RELU) {
                v0 = fmaxf(v0, 0.f); v1 = fmaxf(v1, 0.f);
                v2 = fmaxf(v2, 0.f); v3 = fmaxf(v3, 0.f);
            }
            if (OUT_HALF) {
                __half* C = (__half*)Cv;
                *(unsigned*)&C[(size_t)row*N + col]     = pack_h2(v0, v1);
                *(unsigned*)&C[(size_t)(row+8)*N + col] = pack_h2(v2, v3);
            } else {
                float* C = (float*)Cv;
                *(float2*)&C[(size_t)row*N + col]     = make_float2(v0, v1);
                *(float2*)&C[(size_t)(row+8)*N + col] = make_float2(v2, v3);
            }
        }
    }
}

// ---------------------------------------------------------------------------
// QKV weight prep: g_wqkvT[l][m][e][d] = W_m[l][d][e] (half, n-major)
// ---------------------------------------------------------------------------
__global__ __launch_bounds__(256)
void qkv_wprep(const float* __restrict__ Wq, const float* __restrict__ Wk,
               const float* __restrict__ Wv, __half* __restrict__ out)
{
    const int l = blockIdx.x / 3, m = blockIdx.x % 3;
    const float* W = (m == 0 ? Wq : (m == 1 ? Wk : Wv)) + l*HDIM*HDIM;
    __half* dst = out + ((size_t)l*3 + m)*HDIM*HDIM;
    for (int i = threadIdx.x; i < HDIM*HDIM; i += blockDim.x) {
        int d = i >> 6, e = i & 63;
        dst[e*HDIM + d] = __float2half(W[d*HDIM + e]);
    }
}

// ---------------------------------------------------------------------------
// QKV via fp16 mma: per CTA 128 tokens x 1 head; Q/K/V (N=64 each).
// A-fragments: attention's proven ldsm path; W B-frags: gemm's proven LDS path.
// Writes half [B,H,S,D]; Q scaled 1/32.
// ---------------------------------------------------------------------------
#define QPAD 72
__global__ __launch_bounds__(256)
void qkv_hmma(const __half* __restrict__ hh, const __half* __restrict__ WT,
              __half* __restrict__ Q, __half* __restrict__ K, __half* __restrict__ V)
{
    __shared__ __align__(16) __half As[128][QPAD];    // 18432 B
    __shared__ __align__(16) __half Ws[192][QPAD];    // 27648 B
    const int tid = threadIdx.x, lane = tid & 31, warp = tid >> 5;
    const int t0 = blockIdx.x * 128, head = blockIdx.y;

    // A: 128 rows x 64 halves (2 threads/row, 4 x 16B each)
    {
        const int lr = tid >> 1, lc = (tid & 1) * 32;
        const __half* src = hh + (size_t)(t0 + lr)*EMBED + head*HDIM + lc;
        const uint32_t dst = smem_u32(&As[lr][lc]);
        CP_ASYNC16(dst,      src);
        CP_ASYNC16(dst + 16, src + 8);
        CP_ASYNC16(dst + 32, src + 16);
        CP_ASYNC16(dst + 48, src + 24);
    }
    // W: 192 rows x 64 halves = 1536 x 16B chunks, 6 per thread
    #pragma unroll
    for (int j = 0; j < 6; j++) {
        const int ci = tid + 256*j;
        const int row = ci >> 3, off = (ci & 7) * 8;
        CP_ASYNC16(smem_u32(&Ws[row][off]), WT + row*HDIM + off);
    }
    CP_COMMIT(); CP_WAIT(0);
    __syncthreads();

    // A fragments (rows warp*16 .. +16)
    unsigned af[4][4];
    const uint32_t aB = smem_u32(&As[0][0]);
    const uint32_t aRow = warp*16 + (lane & 15);
    const uint32_t aColB = (lane >> 4) * 16;
    #pragma unroll
    for (int kc = 0; kc < 4; kc++)
        ldsm_x4(af[kc], aB + aRow*(QPAD*2) + kc*32 + aColB);

    const int bRow = lane >> 2, bColB = (lane & 3) * 4;
    const int er = lane >> 2, ec = (lane & 3) * 2;
    const int t = t0 + warp*16 + er;
    const int n = t >> 11, s = t & (SEQ - 1);
    __half* outs[3] = {Q, K, V};

    #pragma unroll
    for (int m = 0; m < 3; m++) {
        float acc[8][4];
        #pragma unroll
        for (int nt = 0; nt < 8; nt++)
            #pragma unroll
            for (int r = 0; r < 4; r++) acc[nt][r] = 0.f;

        #pragma unroll
        for (int nt = 0; nt < 8; nt++) {
            const char* nb = (const char*)&Ws[m*64 + nt*8 + bRow][0] + bColB;
            #pragma unroll
            for (int kc = 0; kc < 4; kc++) {
                unsigned b[2];
                b[0] = *(const unsigned*)(nb + kc*32);
                b[1] = *(const unsigned*)(nb + kc*32 + 16);
                mma16816(acc[nt], af[kc], b);
            }
        }

        const float sc = (m == 0) ? 0.03125f : 1.0f;   // exact power of 2
        __half* base  = outs[m] + ((size_t)(n*HEADS + head)*SEQ + s)*HDIM;
        __half* base8 = base + 8*HDIM;                 // token t+8 (same n,s-block)
        #pragma unroll
        for (int nt = 0; nt < 8; nt++) {
            const int col = nt*8 + ec;
            *(unsigned*)(base  + col) = pack_h2(acc[nt][0]*sc, acc[nt][1]*sc);
            *(unsigned*)(base8 + col) = pack_h2(acc[nt][2]*sc, acc[nt][3]*sc);
        }
    }
}

// ---------------------------------------------------------------------------
// fp16 mma.sync flash attention (R12, proven). Q pre-scaled by 1/32.
// ---------------------------------------------------------------------------
#define APAD 72
#define AROWB (APAD*2)      /* 144 B row stride */

__global__ __launch_bounds__(128)
void attn_mma(const __half* __restrict__ Q, const __half* __restrict__ K,
              const __half* __restrict__ V, __half* __restrict__ O)
{
    __shared__ __align__(16) __half QS[64][APAD];
    __shared__ __align__(16) __half KS[2][64][APAD];
    __shared__ __align__(16) __half VS[2][64][APAD];

    const int tid  = threadIdx.x;
    const int lane = tid & 31, warp = tid >> 5;
    const int qt = blockIdx.x, bh = blockIdx.y;

    const int lr = tid >> 1;
    const int lc = (tid & 1) * 32;
    const size_t gQ = ((size_t)bh*SEQ + qt*64 + lr) * HDIM + lc;
    const uint32_t qDst = smem_u32(&QS[lr][lc]);
    const uint32_t kDst0 = smem_u32(&KS[0][lr][lc]);
    const uint32_t vDst0 = smem_u32(&VS[0][lr][lc]);
    const uint32_t stgB  = smem_u32(&KS[1][0][0]) - smem_u32(&KS[0][0][0]);

    #define LD4(dst, src)                       \
        CP_ASYNC16((dst),      (src));          \
        CP_ASYNC16((dst)+16,   (src)+8);        \
        CP_ASYNC16((dst)+32,   (src)+16);       \
        CP_ASYNC16((dst)+48,   (src)+24);

    {
        const __half* kg = K + ((size_t)bh*SEQ + lr)*HDIM + lc;
        const __half* vg = V + ((size_t)bh*SEQ + lr)*HDIM + lc;
        LD4(qDst, Q + gQ);
        LD4(kDst0, kg);
        LD4(vDst0, vg);
        CP_COMMIT();
    }

    float sacc[8][4], oacc[8][4];
    float mr0 = -1e30f, mr1 = -1e30f, lr0 = 0.f, lr1 = 0.f;
    #pragma unroll
    for (int nt = 0; nt < 8; nt++)
        #pragma unroll
        for (int r = 0; r < 4; r++) oacc[nt][r] = 0.f;

    unsigned qf[4][4];
    const uint32_t aRow  = warp*16 + (lane & 15);
    const uint32_t aColB = (lane >> 4) * 16;
    const int bRow = lane >> 2;
    const int bColB = (lane & 3) * 4;

    const int NT = SEQ / 64;
    for (int kt = 0; kt < NT; kt++) {
        const int cur = kt & 1;
        if (kt + 1 < NT) {
            const __half* kg = K + ((size_t)bh*SEQ + (kt+1)*64 + lr)*HDIM + lc;
            const __half* vg = V + ((size_t)bh*SEQ + (kt+1)*64 + lr)*HDIM + lc;
            LD4(kDst0 + (cur^1)*stgB, kg);
            LD4(vDst0 + (cur^1)*stgB, vg);
            CP_COMMIT();
            CP_WAIT(1);
        } else {
            CP_WAIT(0);
        }
        __syncthreads();

        if (kt == 0) {
            const uint32_t qB = smem_u32(&QS[0][0]);
            #pragma unroll
            for (int kc = 0; kc < 4; kc++)
                ldsm_x4(qf[kc], qB + aRow*AROWB + kc*32 + aColB);
        }

        // ---- S = Q K^T ----
        #pragma unroll
        for (int nt = 0; nt < 8; nt++) {
            #pragma unroll
            for (int r = 0; r < 4; r++) sacc[nt][r] = 0.f;
            const char* nb = (const char*)&KS[cur][nt*8 + bRow][0] + bColB;
            #pragma unroll
            for (int kc = 0; kc < 4; kc++) {
                unsigned b[2];
                b[0] = *(const unsigned*)(nb + kc*32);
                b[1] = *(const unsigned*)(nb + kc*32 + 16);
                mma16816(sacc[nt], qf[kc], b);
            }
        }

        // ---- online softmax ----
        float mx0 = -1e30f, mx1 = -1e30f;
        #pragma unroll
        for (int nt = 0; nt < 8; nt++) {
            mx0 = fmaxf(mx0, fmaxf(sacc[nt][0], sacc[nt][1]));
            mx1 = fmaxf(mx1, fmaxf(sacc[nt][2], sacc[nt][3]));
        }
        mx0 = fmaxf(mx0, __shfl_xor_sync(0xffffffffu, mx0, 1));
        mx0 = fmaxf(mx0, __shfl_xor_sync(0xffffffffu, mx0, 2));
        mx1 = fmaxf(mx1, __shfl_xor_sync(0xffffffffu, mx1, 1));
        mx1 = fmaxf(mx1, __shfl_xor_sync(0xffffffffu, mx1, 2));
        const float nm0 = fmaxf(mr0, mx0), nm1 = fmaxf(mr1, mx1);
        const float fac0 = __expf(mr0 - nm0), fac1 = __expf(mr1 - nm1);
        float sum0 = 0.f, sum1 = 0.f;
        #pragma unroll
        for (int nt = 0; nt < 8; nt++) {
            sacc[nt][0] = __expf(sacc[nt][0] - nm0);
            sacc[nt][1] = __expf(sacc[nt][1] - nm0);
            sacc[nt][2] = __expf(sacc[nt][2] - nm1);
            sacc[nt][3] = __expf(sacc[nt][3] - nm1);
            sum0 += sacc[nt][0] + sacc[nt][1];
            sum1 += sacc[nt][2] + sacc[nt][3];
        }
        sum0 += __shfl_xor_sync(0xffffffffu, sum0, 1);
        sum0 += __shfl_xor_sync(0xffffffffu, sum0, 2);
        sum1 += __shfl_xor_sync(0xffffffffu, sum1, 1);
        sum1 += __shfl_xor_sync(0xffffffffu, sum1, 2);
        lr0 = lr0*fac0 + sum0;  mr0 = nm0;
        lr1 = lr1*fac1 + sum1;  mr1 = nm1;
        #pragma unroll
        for (int nt = 0; nt < 8; nt++) {
            oacc[nt][0] *= fac0; oacc[nt][1] *= fac0;
            oacc[nt][2] *= fac1; oacc[nt][3] *= fac1;
        }

        // ---- P: C-frag -> A-frag ----
        unsigned pa[4][4];
        #pragma unroll
        for (int sc = 0; sc < 4; sc++) {
            pa[sc][0] = pack_h2(sacc[2*sc  ][0], sacc[2*sc  ][1]);
            pa[sc][1] = pack_h2(sacc[2*sc  ][2], sacc[2*sc  ][3]);
            pa[sc][2] = pack_h2(sacc[2*sc+1][0], sacc[2*sc+1][1]);
            pa[sc][3] = pack_h2(sacc[2*sc+1][2], sacc[2*sc+1][3]);
        }

        // ---- O += P V ----
        const uint32_t vB = smem_u32(&VS[cur][0][0]);
        const int g = lane >> 3, r8 = lane & 7;
        #pragma unroll
        for (int sc = 0; sc < 4; sc++) {
            #pragma unroll
            for (int dp = 0; dp < 4; dp++) {
                const uint32_t addr = vB
                    + (sc*16 + ((g & 1) ? 8 : 0) + r8)*AROWB
                    + (dp*16 + ((g >> 1) ? 8 : 0))*2;
                unsigned vf[4];
                ldsm_x4_t(vf, addr);
                mma16816(oacc[2*dp  ], pa[sc], vf);
                mma16816(oacc[2*dp+1], pa[sc], vf + 2);
            }
        }
        __syncthreads();
    }
    #undef LD4

    const int n = bh >> 4, hh = bh & 15;
    const float i0 = 1.f / lr0, i1 = 1.f / lr1;
    const int row0 = qt*64 + warp*16 + (lane >> 2);
    const int t0 = n*SEQ + row0, t1 = t0 + 8;
    #pragma unroll
    for (int dt = 0; dt < 8; dt++) {
        const int col = hh*HDIM + dt*8 + (lane & 3)*2;
        *(unsigned*)&O[(size_t)t0*EMBED + col] = pack_h2(oacc[dt][0]*i0, oacc[dt][1]*i0);
        *(unsigned*)&O[(size_t)t1*EMBED + col] = pack_h2(oacc[dt][2]*i1, oacc[dt][3]*i1);
    }
}

// ---------------------------------------------------------------------------
// 32x32 tiled transpose + fp16 convert
// ---------------------------------------------------------------------------
__global__ __launch_bounds__(256)
void transpose_h(const float* __restrict__ src, __half* __restrict__ dst, int R, int C)
{
    __shared__ float t[32][33];
    const float* s = src + (size_t)blockIdx.z * R * C;
    __half*      d = dst + (size_t)blockIdx.z * R * C;
    int x  = blockIdx.x*32 + threadIdx.x;
    int y0 = blockIdx.y*32;
    #pragma unroll
    for (int j = 0; j < 4; j++)
        t[threadIdx.y + 8*j][threadIdx.x] = s[(size_t)(y0 + threadIdx.y + 8*j)*C + x];
    __syncthreads();
    int x2 = blockIdx.y*32 + threadIdx.x;
    int y2 = blockIdx.x*32;
    #pragma unroll
    for (int j = 0; j < 4; j++)
        d[(size_t)(y2 + threadIdx.y + 8*j)*R + x2] = __float2half(t[threadIdx.x][threadIdx.y + 8*j]);
}

// ---------------------------------------------------------------------------
// Embed: out = x @ W + b + pe (float), plus half copy for QKV
// ---------------------------------------------------------------------------
__global__ __launch_bounds__(256)
void embed_kernel(const float* __restrict__ X, const float* __restrict__ W,
                  const float* __restrict__ bias, const float* __restrict__ pe,
                  float* __restrict__ out, __half* __restrict__ outh)
{
    __shared__ float Xs[64][64];
    __shared__ float Ws[64][64];
    const int tid = threadIdx.x;
    const int tx = tid & 15, ty = tid >> 4;
    const int t0 = blockIdx.x * 64;
    const int c0 = blockIdx.y * 64;

    {
        const int r = tid >> 2, o4 = (tid & 3) * 16;
        const float* xp = X + (size_t)(t0 + r) * 64 + o4;
        const float* wp = W + (size_t)r * EMBED + c0 + o4;
        #pragma unroll
        for (int u = 0; u < 4; u++) {
            *(float4*)&Xs[r][o4 + 4*u] = *(const float4*)(xp + 4*u);
            *(float4*)&Ws[r][o4 + 4*u] = *(const float4*)(wp + 4*u);
        }
    }
    __syncthreads();

    float acc[4][4];
    #pragma unroll
    for (int i = 0; i < 4; i++)
        #pragma unroll
        for (int j = 0; j < 4; j++) acc[i][j] = 0.f;

    #pragma unroll 8
    for (int d = 0; d < 64; d++) {
        float4 wv = *(const float4*)&Ws[d][tx*4];
        #pragma unroll
        for (int i = 0; i < 4; i++) {
            float xr = Xs[ty*4 + i][d];
            acc[i][0] += xr * wv.x;
            acc[i][1] += xr * wv.y;
            acc[i][2] += xr * wv.z;
            acc[i][3] += xr * wv.w;
        }
    }

    float4 bv = *(const float4*)(bias + c0 + tx*4);
    #pragma unroll
    for (int i = 0; i < 4; i++) {
        int t = t0 + ty*4 + i;
        int s = t & (SEQ - 1);
        float4 pv = *(const float4*)(pe + (size_t)s*EMBED + c0 + tx*4);
        float4 r;
        r.x = acc[i][0] + bv.x + pv.x;
        r.y = acc[i][1] + bv.y + pv.y;
        r.z = acc[i][2] + bv.z + pv.z;
        r.w = acc[i][3] + bv.w + pv.w;
        *(float4*)(out + (size_t)t*EMBED + c0 + tx*4) = r;
        uint2 hv;
        hv.x = pack_h2(r.x, r.y);
        hv.y = pack_h2(r.z, r.w);
        *(uint2*)(outh + (size_t)t*EMBED + c0 + tx*4) = hv;
    }
}

// ---------------------------------------------------------------------------
// Fused residual + LayerNorm (+ optional fp16 copy)
// ---------------------------------------------------------------------------
template<int EMIT_H>
__global__ __launch_bounds__(256)
void ln_kernel(const float* __restrict__ A, const float* __restrict__ R,
               const float* __restrict__ gma, const float* __restrict__ bta,
               float* __restrict__ out, __half* __restrict__ outh)
{
    __shared__ float s1[8], s2[8];
    const int t = blockIdx.x, tid = threadIdx.x;
    const size_t base = (size_t)t * EMBED + tid * 4;

    float4 a = *(const float4*)(A + base);
    float4 r = *(const float4*)(R + base);
    float v0 = a.x + r.x, v1 = a.y + r.y, v2 = a.z + r.z, v3 = a.w + r.w;
    float sum = v0 + v1 + v2 + v3;
    float sq  = v0*v0 + v1*v1 + v2*v2 + v3*v3;

    #pragma unroll
    for (int off = 16; off > 0; off >>= 1) {
        sum += __shfl_xor_sync(0xffffffffu, sum, off);
        sq  += __shfl_xor_sync(0xffffffffu, sq,  off);
    }
    if ((tid & 31) == 0) { s1[tid >> 5] = sum; s2[tid >> 5] = sq; }
    __syncthreads();
    if (tid < 32) {
        float ss = (tid < 8) ? s1[tid] : 0.f;
        float qq = (tid < 8) ? s2[tid] : 0.f;
        #pragma unroll
        for (int off = 4; off > 0; off >>= 1) {
            ss += __shfl_xor_sync(0xffffffffu, ss, off);
            qq += __shfl_xor_sync(0xffffffffu, qq, off);
        }
        if (tid == 0) { s1[0] = ss; s2[0] = qq; }
    }
    __syncthreads();

    const float inv = 1.f / (float)EMBED;
    float mu  = s1[0] * inv;
    float var = s2[0] * inv - mu*mu;
    float rstd = rsqrtf(var + 1e-5f);

    float4 g = *(const float4*)(gma + tid*4);
    float4 b = *(const float4*)(bta + tid*4);
    float4 o;
    o.x = (v0 - mu)*rstd*g.x + b.x;
    o.y = (v1 - mu)*rstd*g.y + b.y;
    o.z = (v2 - mu)*rstd*g.z + b.z;
    o.w = (v3 - mu)*rstd*g.w + b.w;
    *(float4*)(out + base) = o;
    if (EMIT_H) {
        uint2 hv;
        hv.x = pack_h2(o.x, o.y);
        hv.y = pack_h2(o.z, o.w);
        *(uint2*)(outh + base) = hv;
    }
}

// ---------------------------------------------------------------------------
extern "C" void kernel_launch(void* const* d_in, const int* in_sizes, int n_in,
                              void* d_out, int out_size)
{
    const float* x       = (const float*)d_in[0];
    // d_in[1] = mask: all-true -> no-op
    const float* embed_W = (const float*)d_in[2];
    const float* embed_b = (const float*)d_in[3];
    const float* pe      = (const float*)d_in[4];
    const float* Wq      = (const float*)d_in[5];
    const float* Wk      = (const float*)d_in[6];
    const float* Wv      = (const float*)d_in[7];
    const float* Wo      = (const float*)d_in[8];
    const float* bo      = (const float*)d_in[9];
    const float* ln1_g   = (const float*)d_in[10];
    const float* ln1_b   = (const float*)d_in[11];
    const float* W1      = (const float*)d_in[12];
    const float* b1      = (const float*)d_in[13];
    const float* W2      = (const float*)d_in[14];
    const float* b2      = (const float*)d_in[15];
    const float* ln2_g   = (const float*)d_in[16];
    const float* ln2_b   = (const float*)d_in[17];
    float* h = (float*)d_out;

    float  *t1, *x1, *t2;
    __half *hhb, *qh, *kh, *vh, *oh, *x1h, *ffh, *woT, *w1T, *w2T, *wqkvT;
    cudaGetSymbolAddress((void**)&hhb, g_hh);
    cudaGetSymbolAddress((void**)&qh,  g_qh);
    cudaGetSymbolAddress((void**)&kh,  g_kh);
    cudaGetSymbolAddress((void**)&vh,  g_vh);
    cudaGetSymbolAddress((void**)&t1,  g_t1);
    cudaGetSymbolAddress((void**)&x1,  g_x1);
    cudaGetSymbolAddress((void**)&t2,  g_t2);
    cudaGetSymbolAddress((void**)&oh,  g_oh);
    cudaGetSymbolAddress((void**)&x1h, g_x1h);
    cudaGetSymbolAddress((void**)&ffh, g_ffh);
    cudaGetSymbolAddress((void**)&woT, g_woT);
    cudaGetSymbolAddress((void**)&w1T, g_w1T);
    cudaGetSymbolAddress((void**)&w2T, g_w2T);
    cudaGetSymbolAddress((void**)&wqkvT, g_wqkvT);

    cudaFuncSetAttribute(gemm_hmma<0,0>, cudaFuncAttributeMaxDynamicSharedMemorySize, GEMM_DSMEM);
    cudaFuncSetAttribute(gemm_hmma<1,1>, cudaFuncAttributeMaxDynamicSharedMemorySize, GEMM_DSMEM);

    transpose_h<<<dim3(EMBED/32, EMBED/32, 3), dim3(32,8)>>>(Wo, woT, EMBED, EMBED);
    transpose_h<<<dim3(FFN/32,   EMBED/32, 3), dim3(32,8)>>>(W1, w1T, EMBED, FFN);
    transpose_h<<<dim3(EMBED/32, FFN/32,   3), dim3(32,8)>>>(W2, w2T, FFN, EMBED);
    qkv_wprep<<<9, 256>>>(Wq, Wk, Wv, wqkvT);

    embed_kernel<<<dim3(TOK/64, EMBED/64), 256>>>(x, embed_W, embed_b, pe, h, hhb);

    for (int l = 0; l < 3; l++) {
        qkv_hmma<<<dim3(TOK/128, HEADS), 256>>>(
            hhb, wqkvT + (size_t)l*3*HDIM*HDIM, qh, kh, vh);

        attn_mma<<<dim3(SEQ/64, BATCH*HEADS), 128>>>(qh, kh, vh, oh);

        gemm_hmma<0,0><<<dim3(EMBED/128, TOK/128), 256, GEMM_DSMEM>>>(
            oh, woT + (size_t)l*EMBED*EMBED, bo + l*EMBED, t1, TOK, EMBED, EMBED);

        ln_kernel<1><<<TOK, 256>>>(t1, h, ln1_g + l*EMBED, ln1_b + l*EMBED, x1, x1h);

        gemm_hmma<1,1><<<dim3(FFN/128, TOK/128), 256, GEMM_DSMEM>>>(
            x1h, w1T + (size_t)l*EMBED*FFN, b1 + l*FFN, ffh, TOK, FFN, EMBED);

        gemm_hmma<0,0><<<dim3(EMBED/128, TOK/128), 256, GEMM_DSMEM>>>(
            ffh, w2T + (size_t)l*FFN*EMBED, b2 + l*EMBED, t2, TOK, EMBED, FFN);

        ln_kernel<1><<<TOK, 256>>>(t2, x1, ln2_g + l*EMBED, ln2_b + l*EMBED, h, hhb);
    }
}

// round 14
// speedup vs baseline: 5.8473x; 1.0516x over previous
#include <cuda_runtime.h>
#include <cuda_fp16.h>
#include <math.h>
#include <stdint.h>

#define SEQ   2048
#define BATCH 2
#define EMBED 1024
#define HEADS 16
#define HDIM  64
#define FFN   4096
#define TOK   (BATCH*SEQ)   /* 4096 tokens */

// ---------------- scratch (device globals; no allocations allowed) ----------
static __device__ __half g_hh [TOK*EMBED];            // half copy of h (QKV input)
static __device__ __half g_qh [TOK*EMBED];            // Q (pre-scaled 1/32) [B,H,S,D]
static __device__ __half g_kh [TOK*EMBED];            // K [B,H,S,D]
static __device__ __half g_vh [TOK*EMBED];            // V [B,H,S,D]
static __device__ float  g_t1 [TOK*EMBED];
static __device__ float  g_x1 [TOK*EMBED];
static __device__ float  g_t2 [TOK*EMBED];
static __device__ __half g_oh [TOK*EMBED];            // attn out (GEMM A)
static __device__ __half g_x1h[TOK*EMBED];            // ln1 out (GEMM A)
static __device__ __half g_ffh[(size_t)TOK*FFN];      // relu(ffn1) (GEMM A)
static __device__ __half g_woT[3*EMBED*EMBED];        // half, k-major BT[n][k]
static __device__ __half g_w1T[(size_t)3*EMBED*FFN];
static __device__ __half g_w2T[(size_t)3*FFN*EMBED];
static __device__ __half g_wqkvT[3*3*HDIM*HDIM];      // [layer][q/k/v][e][d] half

// ---------------------------------------------------------------------------
// helpers
// ---------------------------------------------------------------------------
__device__ __forceinline__ uint32_t smem_u32(const void* p) {
    uint32_t a;
    asm("{ .reg .u64 t; cvta.to.shared.u64 t, %1; cvt.u32.u64 %0, t; }"
        : "=r"(a) : "l"(p));
    return a;
}
__device__ __forceinline__ void ldsm_x4(unsigned* r, uint32_t addr) {
    asm volatile("ldmatrix.sync.aligned.m8n8.x4.shared.b16 {%0,%1,%2,%3}, [%4];"
                 : "=r"(r[0]), "=r"(r[1]), "=r"(r[2]), "=r"(r[3]) : "r"(addr));
}
__device__ __forceinline__ void ldsm_x4_t(unsigned* r, uint32_t addr) {
    asm volatile("ldmatrix.sync.aligned.m8n8.x4.trans.shared.b16 {%0,%1,%2,%3}, [%4];"
                 : "=r"(r[0]), "=r"(r[1]), "=r"(r[2]), "=r"(r[3]) : "r"(addr));
}
__device__ __forceinline__ void mma16816(float* c, const unsigned* a, const unsigned* b) {
    asm volatile(
        "mma.sync.aligned.m16n8k16.row.col.f32.f16.f16.f32 "
        "{%0,%1,%2,%3}, {%4,%5,%6,%7}, {%8,%9}, {%0,%1,%2,%3};"
        : "+f"(c[0]), "+f"(c[1]), "+f"(c[2]), "+f"(c[3])
        : "r"(a[0]), "r"(a[1]), "r"(a[2]), "r"(a[3]), "r"(b[0]), "r"(b[1]));
}
// pack two fp32 into f16x2: lo = x, hi = y
__device__ __forceinline__ uint32_t pack_h2(float x, float y) {
    uint32_t r;
    asm("cvt.rn.f16x2.f32 %0, %1, %2;" : "=r"(r) : "f"(y), "f"(x));
    return r;
}
#define CP_ASYNC16(dst, src) \
    asm volatile("cp.async.cg.shared.global [%0], [%1], 16;" :: "r"(dst), "l"(src) : "memory")
#define CP_COMMIT()  asm volatile("cp.async.commit_group;" ::: "memory")
#define CP_WAIT(n)   asm volatile("cp.async.wait_group %0;" :: "n"(n) : "memory")

// ---------------------------------------------------------------------------
// fp16 mma.sync GEMM, 3-stage cp.async pipeline (R13, proven).
// ---------------------------------------------------------------------------
#define SSTR   56
#define STG_B  (128*SSTR*2)          /* 14336 B per operand stage */
#define GEMM_DSMEM (6*STG_B)         /* 86016 B */

template<int RELU, int OUT_HALF>
__global__ __launch_bounds__(256, 2)
void gemm_hmma(const __half* __restrict__ A, const __half* __restrict__ BT,
               const float* __restrict__ bias, void* __restrict__ Cv,
               int M, int N, int K)
{
    extern __shared__ __align__(16) char dsm[];
    const int tid  = threadIdx.x;
    const int lane = tid & 31, warp = tid >> 5;
    const int m0w = (warp >> 2) * 64;
    const int n0w = (warp & 3) * 32;
    const int rowBase = blockIdx.y * 128;
    const int colBase = blockIdx.x * 128;

    const uint32_t sb = smem_u32(dsm);
    const uint32_t aS = sb;
    const uint32_t bS = sb + 3*STG_B;

    const int lr = tid >> 1, lo = (tid & 1) * 16;
    const __half* Ag = A  + (size_t)(rowBase + lr) * K + lo;
    const __half* Bg = BT + (size_t)(colBase + lr) * K + lo;
    const uint32_t stOff = lr*(SSTR*2) + lo*2;

    float acc[4][4][4];
    #pragma unroll
    for (int mt = 0; mt < 4; mt++)
        #pragma unroll
        for (int nt = 0; nt < 4; nt++)
            #pragma unroll
            for (int r = 0; r < 4; r++) acc[mt][nt][r] = 0.f;

    #define ISSUE(c, stg)                                   \
    {                                                       \
        const __half* ag = Ag + (size_t)(c)*32;             \
        const __half* bg = Bg + (size_t)(c)*32;             \
        uint32_t ad = aS + (stg)*STG_B + stOff;             \
        uint32_t bd = bS + (stg)*STG_B + stOff;             \
        CP_ASYNC16(ad,      ag);                            \
        CP_ASYNC16(ad + 16, ag + 8);                        \
        CP_ASYNC16(bd,      bg);                            \
        CP_ASYNC16(bd + 16, bg + 8);                        \
        CP_COMMIT();                                        \
    }

    const int NC = K >> 5;
    ISSUE(0, 0);
    ISSUE(1, 1);

    const uint32_t aRow  = m0w + (lane & 15);
    const uint32_t aColB = ((lane >> 4) * 8) * 2;
    const uint32_t bRowB = (n0w + (lane >> 2)) * (SSTR*2);
    const uint32_t bColB = (lane & 3) * 4;

    for (int c = 0; c < NC; c++) {
        if (c + 1 < NC) CP_WAIT(1); else CP_WAIT(0);
        __syncthreads();
        if (c + 2 < NC) { const int ns = (c + 2) % 3; ISSUE(c + 2, ns); }

        const int cur = c % 3;
        const uint32_t aSt = aS + cur*STG_B;
        const char*    bPt = dsm + 3*STG_B + cur*STG_B + bRowB + bColB;
        #pragma unroll
        for (int s = 0; s < 2; s++) {
            const uint32_t k0B = s * 32;
            unsigned af[4][4], bf[4][2];
            #pragma unroll
            for (int mt = 0; mt < 4; mt++)
                ldsm_x4(af[mt], aSt + (aRow + mt*16)*(SSTR*2) + k0B + aColB);
            #pragma unroll
            for (int nt = 0; nt < 4; nt++) {
                const char* nb = bPt + nt*8*(SSTR*2) + k0B;
                bf[nt][0] = *(const unsigned*)(nb);
                bf[nt][1] = *(const unsigned*)(nb + 16);
            }
            #pragma unroll
            for (int mt = 0; mt < 4; mt++)
                #pragma unroll
                for (int nt = 0; nt < 4; nt++)
                    mma16816(acc[mt][nt], af[mt], bf[nt]);
        }
    }
    #undef ISSUE

    const int er = lane >> 2, ec = (lane & 3) * 2;
    #pragma unroll
    for (int mt = 0; mt < 4; mt++) {
        const int row = rowBase + m0w + mt*16 + er;
        #pragma unroll
        for (int nt = 0; nt < 4; nt++) {
            const int col = colBase + n0w + nt*8 + ec;
            float2 bv = *(const float2*)(bias + col);
            float v0 = acc[mt][nt][0] + bv.x;
            float v1 = acc[mt][nt][1] + bv.y;
            float v2 = acc[mt][nt][2] + bv.x;
            float v3 = acc[mt][nt][3] + bv.y;
            if (RELU) {
                v0 = fmaxf(v0, 0.f); v1 = fmaxf(v1, 0.f);
                v2 = fmaxf(v2, 0.f); v3 = fmaxf(v3, 0.f);
            }
            if (OUT_HALF) {
                __half* C = (__half*)Cv;
                *(unsigned*)&C[(size_t)row*N + col]     = pack_h2(v0, v1);
                *(unsigned*)&C[(size_t)(row+8)*N + col] = pack_h2(v2, v3);
            } else {
                float* C = (float*)Cv;
                *(float2*)&C[(size_t)row*N + col]     = make_float2(v0, v1);
                *(float2*)&C[(size_t)(row+8)*N + col] = make_float2(v2, v3);
            }
        }
    }
}

// ---------------------------------------------------------------------------
// QKV weight prep (R13, proven)
// ---------------------------------------------------------------------------
__global__ __launch_bounds__(256)
void qkv_wprep(const float* __restrict__ Wq, const float* __restrict__ Wk,
               const float* __restrict__ Wv, __half* __restrict__ out)
{
    const int l = blockIdx.x / 3, m = blockIdx.x % 3;
    const float* W = (m == 0 ? Wq : (m == 1 ? Wk : Wv)) + l*HDIM*HDIM;
    __half* dst = out + ((size_t)l*3 + m)*HDIM*HDIM;
    for (int i = threadIdx.x; i < HDIM*HDIM; i += blockDim.x) {
        int d = i >> 6, e = i & 63;
        dst[e*HDIM + d] = __float2half(W[d*HDIM + e]);
    }
}

// ---------------------------------------------------------------------------
// QKV via fp16 mma (R13, proven)
// ---------------------------------------------------------------------------
#define QPAD 72
__global__ __launch_bounds__(256)
void qkv_hmma(const __half* __restrict__ hh, const __half* __restrict__ WT,
              __half* __restrict__ Q, __half* __restrict__ K, __half* __restrict__ V)
{
    __shared__ __align__(16) __half As[128][QPAD];
    __shared__ __align__(16) __half Ws[192][QPAD];
    const int tid = threadIdx.x, lane = tid & 31, warp = tid >> 5;
    const int t0 = blockIdx.x * 128, head = blockIdx.y;

    {
        const int lr = tid >> 1, lc = (tid & 1) * 32;
        const __half* src = hh + (size_t)(t0 + lr)*EMBED + head*HDIM + lc;
        const uint32_t dst = smem_u32(&As[lr][lc]);
        CP_ASYNC16(dst,      src);
        CP_ASYNC16(dst + 16, src + 8);
        CP_ASYNC16(dst + 32, src + 16);
        CP_ASYNC16(dst + 48, src + 24);
    }
    #pragma unroll
    for (int j = 0; j < 6; j++) {
        const int ci = tid + 256*j;
        const int row = ci >> 3, off = (ci & 7) * 8;
        CP_ASYNC16(smem_u32(&Ws[row][off]), WT + row*HDIM + off);
    }
    CP_COMMIT(); CP_WAIT(0);
    __syncthreads();

    unsigned af[4][4];
    const uint32_t aB = smem_u32(&As[0][0]);
    const uint32_t aRow = warp*16 + (lane & 15);
    const uint32_t aColB = (lane >> 4) * 16;
    #pragma unroll
    for (int kc = 0; kc < 4; kc++)
        ldsm_x4(af[kc], aB + aRow*(QPAD*2) + kc*32 + aColB);

    const int bRow = lane >> 2, bColB = (lane & 3) * 4;
    const int er = lane >> 2, ec = (lane & 3) * 2;
    const int t = t0 + warp*16 + er;
    const int n = t >> 11, s = t & (SEQ - 1);
    __half* outs[3] = {Q, K, V};

    #pragma unroll
    for (int m = 0; m < 3; m++) {
        float acc[8][4];
        #pragma unroll
        for (int nt = 0; nt < 8; nt++)
            #pragma unroll
            for (int r = 0; r < 4; r++) acc[nt][r] = 0.f;

        #pragma unroll
        for (int nt = 0; nt < 8; nt++) {
            const char* nb = (const char*)&Ws[m*64 + nt*8 + bRow][0] + bColB;
            #pragma unroll
            for (int kc = 0; kc < 4; kc++) {
                unsigned b[2];
                b[0] = *(const unsigned*)(nb + kc*32);
                b[1] = *(const unsigned*)(nb + kc*32 + 16);
                mma16816(acc[nt], af[kc], b);
            }
        }

        const float sc = (m == 0) ? 0.03125f : 1.0f;
        __half* base  = outs[m] + ((size_t)(n*HEADS + head)*SEQ + s)*HDIM;
        __half* base8 = base + 8*HDIM;
        #pragma unroll
        for (int nt = 0; nt < 8; nt++) {
            const int col = nt*8 + ec;
            *(unsigned*)(base  + col) = pack_h2(acc[nt][0]*sc, acc[nt][1]*sc);
            *(unsigned*)(base8 + col) = pack_h2(acc[nt][2]*sc, acc[nt][3]*sc);
        }
    }
}

// ---------------------------------------------------------------------------
// fp16 mma.sync flash attention, 128 q-rows/CTA (8 warps).
// Per-warp math identical to the proven 4-warp version; q-tile doubled to
// halve K/V HBM re-reads. Dynamic smem 55296 B: Q[128][72] K[2][64][72] V[2][64][72].
// ---------------------------------------------------------------------------
#define APAD 72
#define AROWB (APAD*2)      /* 144 B row stride */
#define ATTN_QS    0
#define ATTN_KS    (128*AROWB)                 /* 18432 */
#define ATTN_VS    (ATTN_KS + 2*64*AROWB)      /* 36864 */
#define ATTN_DSMEM (ATTN_VS + 2*64*AROWB)      /* 55296 */

__global__ __launch_bounds__(256)
void attn_mma(const __half* __restrict__ Q, const __half* __restrict__ K,
              const __half* __restrict__ V, __half* __restrict__ O)
{
    extern __shared__ __align__(16) char asm_[];
    const uint32_t sb = smem_u32(asm_);
    const uint32_t qB0 = sb + ATTN_QS;
    const uint32_t kB0 = sb + ATTN_KS;
    const uint32_t vB0 = sb + ATTN_VS;
    const uint32_t stgB = 64*AROWB;

    const int tid  = threadIdx.x;
    const int lane = tid & 31, warp = tid >> 5;
    const int qt = blockIdx.x, bh = blockIdx.y;

    // Q loader: 128 rows, 2 threads/row, 4x16B each
    const int qlr = tid >> 1, qlc = (tid & 1) * 32;
    // K/V loader: 64 rows, 4 threads/row, 16 halves (2x16B) each
    const int klr = tid >> 2, klc = (tid & 3) * 16;

    {
        const __half* qg = Q + ((size_t)bh*SEQ + qt*128 + qlr)*HDIM + qlc;
        const uint32_t qd = qB0 + qlr*AROWB + qlc*2;
        CP_ASYNC16(qd,      qg);
        CP_ASYNC16(qd + 16, qg + 8);
        CP_ASYNC16(qd + 32, qg + 16);
        CP_ASYNC16(qd + 48, qg + 24);
        const __half* kg = K + ((size_t)bh*SEQ + klr)*HDIM + klc;
        const __half* vg = V + ((size_t)bh*SEQ + klr)*HDIM + klc;
        const uint32_t kd = kB0 + klr*AROWB + klc*2;
        const uint32_t vd = vB0 + klr*AROWB + klc*2;
        CP_ASYNC16(kd,      kg);
        CP_ASYNC16(kd + 16, kg + 8);
        CP_ASYNC16(vd,      vg);
        CP_ASYNC16(vd + 16, vg + 8);
        CP_COMMIT();
    }

    float sacc[8][4], oacc[8][4];
    float mr0 = -1e30f, mr1 = -1e30f, lr0 = 0.f, lr1 = 0.f;
    #pragma unroll
    for (int nt = 0; nt < 8; nt++)
        #pragma unroll
        for (int r = 0; r < 4; r++) oacc[nt][r] = 0.f;

    unsigned qf[4][4];
    const uint32_t aRow  = warp*16 + (lane & 15);
    const uint32_t aColB = (lane >> 4) * 16;
    const int bRow = lane >> 2;
    const int bColB = (lane & 3) * 4;

    const int NT = SEQ / 64;
    for (int kt = 0; kt < NT; kt++) {
        const int cur = kt & 1;
        if (kt + 1 < NT) {
            const __half* kg = K + ((size_t)bh*SEQ + (kt+1)*64 + klr)*HDIM + klc;
            const __half* vg = V + ((size_t)bh*SEQ + (kt+1)*64 + klr)*HDIM + klc;
            const uint32_t kd = kB0 + (cur^1)*stgB + klr*AROWB + klc*2;
            const uint32_t vd = vB0 + (cur^1)*stgB + klr*AROWB + klc*2;
            CP_ASYNC16(kd,      kg);
            CP_ASYNC16(kd + 16, kg + 8);
            CP_ASYNC16(vd,      vg);
            CP_ASYNC16(vd + 16, vg + 8);
            CP_COMMIT();
            CP_WAIT(1);
        } else {
            CP_WAIT(0);
        }
        __syncthreads();

        if (kt == 0) {
            #pragma unroll
            for (int kc = 0; kc < 4; kc++)
                ldsm_x4(qf[kc], qB0 + aRow*AROWB + kc*32 + aColB);
        }

        // ---- S = Q K^T ----
        const uint32_t kB = kB0 + cur*stgB;
        #pragma unroll
        for (int nt = 0; nt < 8; nt++) {
            #pragma unroll
            for (int r = 0; r < 4; r++) sacc[nt][r] = 0.f;
            const uint32_t nb = kB + (nt*8 + bRow)*AROWB + bColB;
            #pragma unroll
            for (int kc = 0; kc < 4; kc++) {
                unsigned b[2];
                asm volatile("ld.shared.u32 %0, [%1];" : "=r"(b[0]) : "r"(nb + kc*32));
                asm volatile("ld.shared.u32 %0, [%1];" : "=r"(b[1]) : "r"(nb + kc*32 + 16));
                mma16816(sacc[nt], qf[kc], b);
            }
        }

        // ---- online softmax ----
        float mx0 = -1e30f, mx1 = -1e30f;
        #pragma unroll
        for (int nt = 0; nt < 8; nt++) {
            mx0 = fmaxf(mx0, fmaxf(sacc[nt][0], sacc[nt][1]));
            mx1 = fmaxf(mx1, fmaxf(sacc[nt][2], sacc[nt][3]));
        }
        mx0 = fmaxf(mx0, __shfl_xor_sync(0xffffffffu, mx0, 1));
        mx0 = fmaxf(mx0, __shfl_xor_sync(0xffffffffu, mx0, 2));
        mx1 = fmaxf(mx1, __shfl_xor_sync(0xffffffffu, mx1, 1));
        mx1 = fmaxf(mx1, __shfl_xor_sync(0xffffffffu, mx1, 2));
        const float nm0 = fmaxf(mr0, mx0), nm1 = fmaxf(mr1, mx1);
        const float fac0 = __expf(mr0 - nm0), fac1 = __expf(mr1 - nm1);
        float sum0 = 0.f, sum1 = 0.f;
        #pragma unroll
        for (int nt = 0; nt < 8; nt++) {
            sacc[nt][0] = __expf(sacc[nt][0] - nm0);
            sacc[nt][1] = __expf(sacc[nt][1] - nm0);
            sacc[nt][2] = __expf(sacc[nt][2] - nm1);
            sacc[nt][3] = __expf(sacc[nt][3] - nm1);
            sum0 += sacc[nt][0] + sacc[nt][1];
            sum1 += sacc[nt][2] + sacc[nt][3];
        }
        sum0 += __shfl_xor_sync(0xffffffffu, sum0, 1);
        sum0 += __shfl_xor_sync(0xffffffffu, sum0, 2);
        sum1 += __shfl_xor_sync(0xffffffffu, sum1, 1);
        sum1 += __shfl_xor_sync(0xffffffffu, sum1, 2);
        lr0 = lr0*fac0 + sum0;  mr0 = nm0;
        lr1 = lr1*fac1 + sum1;  mr1 = nm1;
        #pragma unroll
        for (int nt = 0; nt < 8; nt++) {
            oacc[nt][0] *= fac0; oacc[nt][1] *= fac0;
            oacc[nt][2] *= fac1; oacc[nt][3] *= fac1;
        }

        // ---- P: C-frag -> A-frag ----
        unsigned pa[4][4];
        #pragma unroll
        for (int sc = 0; sc < 4; sc++) {
            pa[sc][0] = pack_h2(sacc[2*sc  ][0], sacc[2*sc  ][1]);
            pa[sc][1] = pack_h2(sacc[2*sc  ][2], sacc[2*sc  ][3]);
            pa[sc][2] = pack_h2(sacc[2*sc+1][0], sacc[2*sc+1][1]);
            pa[sc][3] = pack_h2(sacc[2*sc+1][2], sacc[2*sc+1][3]);
        }

        // ---- O += P V ----
        const uint32_t vB = vB0 + cur*stgB;
        const int g = lane >> 3, r8 = lane & 7;
        #pragma unroll
        for (int sc = 0; sc < 4; sc++) {
            #pragma unroll
            for (int dp = 0; dp < 4; dp++) {
                const uint32_t addr = vB
                    + (sc*16 + ((g & 1) ? 8 : 0) + r8)*AROWB
                    + (dp*16 + ((g >> 1) ? 8 : 0))*2;
                unsigned vf[4];
                ldsm_x4_t(vf, addr);
                mma16816(oacc[2*dp  ], pa[sc], vf);
                mma16816(oacc[2*dp+1], pa[sc], vf + 2);
            }
        }
        __syncthreads();
    }

    const int n = bh >> 4, hh = bh & 15;
    const float i0 = 1.f / lr0, i1 = 1.f / lr1;
    const int row0 = qt*128 + warp*16 + (lane >> 2);
    const int t0 = n*SEQ + row0, t1 = t0 + 8;
    #pragma unroll
    for (int dt = 0; dt < 8; dt++) {
        const int col = hh*HDIM + dt*8 + (lane & 3)*2;
        *(unsigned*)&O[(size_t)t0*EMBED + col] = pack_h2(oacc[dt][0]*i0, oacc[dt][1]*i0);
        *(unsigned*)&O[(size_t)t1*EMBED + col] = pack_h2(oacc[dt][2]*i1, oacc[dt][3]*i1);
    }
}

// ---------------------------------------------------------------------------
// 32x32 tiled transpose + fp16 convert
// ---------------------------------------------------------------------------
__global__ __launch_bounds__(256)
void transpose_h(const float* __restrict__ src, __half* __restrict__ dst, int R, int C)
{
    __shared__ float t[32][33];
    const float* s = src + (size_t)blockIdx.z * R * C;
    __half*      d = dst + (size_t)blockIdx.z * R * C;
    int x  = blockIdx.x*32 + threadIdx.x;
    int y0 = blockIdx.y*32;
    #pragma unroll
    for (int j = 0; j < 4; j++)
        t[threadIdx.y + 8*j][threadIdx.x] = s[(size_t)(y0 + threadIdx.y + 8*j)*C + x];
    __syncthreads();
    int x2 = blockIdx.y*32 + threadIdx.x;
    int y2 = blockIdx.x*32;
    #pragma unroll
    for (int j = 0; j < 4; j++)
        d[(size_t)(y2 + threadIdx.y + 8*j)*R + x2] = __float2half(t[threadIdx.x][threadIdx.y + 8*j]);
}

// ---------------------------------------------------------------------------
// Embed: out = x @ W + b + pe (float), plus half copy for QKV
// ---------------------------------------------------------------------------
__global__ __launch_bounds__(256)
void embed_kernel(const float* __restrict__ X, const float* __restrict__ W,
                  const float* __restrict__ bias, const float* __restrict__ pe,
                  float* __restrict__ out, __half* __restrict__ outh)
{
    __shared__ float Xs[64][64];
    __shared__ float Ws[64][64];
    const int tid = threadIdx.x;
    const int tx = tid & 15, ty = tid >> 4;
    const int t0 = blockIdx.x * 64;
    const int c0 = blockIdx.y * 64;

    {
        const int r = tid >> 2, o4 = (tid & 3) * 16;
        const float* xp = X + (size_t)(t0 + r) * 64 + o4;
        const float* wp = W + (size_t)r * EMBED + c0 + o4;
        #pragma unroll
        for (int u = 0; u < 4; u++) {
            *(float4*)&Xs[r][o4 + 4*u] = *(const float4*)(xp + 4*u);
            *(float4*)&Ws[r][o4 + 4*u] = *(const float4*)(wp + 4*u);
        }
    }
    __syncthreads();

    float acc[4][4];
    #pragma unroll
    for (int i = 0; i < 4; i++)
        #pragma unroll
        for (int j = 0; j < 4; j++) acc[i][j] = 0.f;

    #pragma unroll 8
    for (int d = 0; d < 64; d++) {
        float4 wv = *(const float4*)&Ws[d][tx*4];
        #pragma unroll
        for (int i = 0; i < 4; i++) {
            float xr = Xs[ty*4 + i][d];
            acc[i][0] += xr * wv.x;
            acc[i][1] += xr * wv.y;
            acc[i][2] += xr * wv.z;
            acc[i][3] += xr * wv.w;
        }
    }

    float4 bv = *(const float4*)(bias + c0 + tx*4);
    #pragma unroll
    for (int i = 0; i < 4; i++) {
        int t = t0 + ty*4 + i;
        int s = t & (SEQ - 1);
        float4 pv = *(const float4*)(pe + (size_t)s*EMBED + c0 + tx*4);
        float4 r;
        r.x = acc[i][0] + bv.x + pv.x;
        r.y = acc[i][1] + bv.y + pv.y;
        r.z = acc[i][2] + bv.z + pv.z;
        r.w = acc[i][3] + bv.w + pv.w;
        *(float4*)(out + (size_t)t*EMBED + c0 + tx*4) = r;
        uint2 hv;
        hv.x = pack_h2(r.x, r.y);
        hv.y = pack_h2(r.z, r.w);
        *(uint2*)(outh + (size_t)t*EMBED + c0 + tx*4) = hv;
    }
}

// ---------------------------------------------------------------------------
// Fused residual + LayerNorm (+ optional fp16 copy)
// ---------------------------------------------------------------------------
template<int EMIT_H>
__global__ __launch_bounds__(256)
void ln_kernel(const float* __restrict__ A, const float* __restrict__ R,
               const float* __restrict__ gma, const float* __restrict__ bta,
               float* __restrict__ out, __half* __restrict__ outh)
{
    __shared__ float s1[8], s2[8];
    const int t = blockIdx.x, tid = threadIdx.x;
    const size_t base = (size_t)t * EMBED + tid * 4;

    float4 a = *(const float4*)(A + base);
    float4 r = *(const float4*)(R + base);
    float v0 = a.x + r.x, v1 = a.y + r.y, v2 = a.z + r.z, v3 = a.w + r.w;
    float sum = v0 + v1 + v2 + v3;
    float sq  = v0*v0 + v1*v1 + v2*v2 + v3*v3;

    #pragma unroll
    for (int off = 16; off > 0; off >>= 1) {
        sum += __shfl_xor_sync(0xffffffffu, sum, off);
        sq  += __shfl_xor_sync(0xffffffffu, sq,  off);
    }
    if ((tid & 31) == 0) { s1[tid >> 5] = sum; s2[tid >> 5] = sq; }
    __syncthreads();
    if (tid < 32) {
        float ss = (tid < 8) ? s1[tid] : 0.f;
        float qq = (tid < 8) ? s2[tid] : 0.f;
        #pragma unroll
        for (int off = 4; off > 0; off >>= 1) {
            ss += __shfl_xor_sync(0xffffffffu, ss, off);
            qq += __shfl_xor_sync(0xffffffffu, qq, off);
        }
        if (tid == 0) { s1[0] = ss; s2[0] = qq; }
    }
    __syncthreads();

    const float inv = 1.f / (float)EMBED;
    float mu  = s1[0] * inv;
    float var = s2[0] * inv - mu*mu;
    float rstd = rsqrtf(var + 1e-5f);

    float4 g = *(const float4*)(gma + tid*4);
    float4 b = *(const float4*)(bta + tid*4);
    float4 o;
    o.x = (v0 - mu)*rstd*g.x + b.x;
    o.y = (v1 - mu)*rstd*g.y + b.y;
    o.z = (v2 - mu)*rstd*g.z + b.z;
    o.w = (v3 - mu)*rstd*g.w + b.w;
    *(float4*)(out + base) = o;
    if (EMIT_H) {
        uint2 hv;
        hv.x = pack_h2(o.x, o.y);
        hv.y = pack_h2(o.z, o.w);
        *(uint2*)(outh + base) = hv;
    }
}

// ---------------------------------------------------------------------------
extern "C" void kernel_launch(void* const* d_in, const int* in_sizes, int n_in,
                              void* d_out, int out_size)
{
    const float* x       = (const float*)d_in[0];
    // d_in[1] = mask: all-true -> no-op
    const float* embed_W = (const float*)d_in[2];
    const float* embed_b = (const float*)d_in[3];
    const float* pe      = (const float*)d_in[4];
    const float* Wq      = (const float*)d_in[5];
    const float* Wk      = (const float*)d_in[6];
    const float* Wv      = (const float*)d_in[7];
    const float* Wo      = (const float*)d_in[8];
    const float* bo      = (const float*)d_in[9];
    const float* ln1_g   = (const float*)d_in[10];
    const float* ln1_b   = (const float*)d_in[11];
    const float* W1      = (const float*)d_in[12];
    const float* b1      = (const float*)d_in[13];
    const float* W2      = (const float*)d_in[14];
    const float* b2      = (const float*)d_in[15];
    const float* ln2_g   = (const float*)d_in[16];
    const float* ln2_b   = (const float*)d_in[17];
    float* h = (float*)d_out;

    float  *t1, *x1, *t2;
    __half *hhb, *qh, *kh, *vh, *oh, *x1h, *ffh, *woT, *w1T, *w2T, *wqkvT;
    cudaGetSymbolAddress((void**)&hhb, g_hh);
    cudaGetSymbolAddress((void**)&qh,  g_qh);
    cudaGetSymbolAddress((void**)&kh,  g_kh);
    cudaGetSymbolAddress((void**)&vh,  g_vh);
    cudaGetSymbolAddress((void**)&t1,  g_t1);
    cudaGetSymbolAddress((void**)&x1,  g_x1);
    cudaGetSymbolAddress((void**)&t2,  g_t2);
    cudaGetSymbolAddress((void**)&oh,  g_oh);
    cudaGetSymbolAddress((void**)&x1h, g_x1h);
    cudaGetSymbolAddress((void**)&ffh, g_ffh);
    cudaGetSymbolAddress((void**)&woT, g_woT);
    cudaGetSymbolAddress((void**)&w1T, g_w1T);
    cudaGetSymbolAddress((void**)&w2T, g_w2T);
    cudaGetSymbolAddress((void**)&wqkvT, g_wqkvT);

    cudaFuncSetAttribute(gemm_hmma<0,0>, cudaFuncAttributeMaxDynamicSharedMemorySize, GEMM_DSMEM);
    cudaFuncSetAttribute(gemm_hmma<1,1>, cudaFuncAttributeMaxDynamicSharedMemorySize, GEMM_DSMEM);
    cudaFuncSetAttribute(attn_mma, cudaFuncAttributeMaxDynamicSharedMemorySize, ATTN_DSMEM);

    transpose_h<<<dim3(EMBED/32, EMBED/32, 3), dim3(32,8)>>>(Wo, woT, EMBED, EMBED);
    transpose_h<<<dim3(FFN/32,   EMBED/32, 3), dim3(32,8)>>>(W1, w1T, EMBED, FFN);
    transpose_h<<<dim3(EMBED/32, FFN/32,   3), dim3(32,8)>>>(W2, w2T, FFN, EMBED);
    qkv_wprep<<<9, 256>>>(Wq, Wk, Wv, wqkvT);

    embed_kernel<<<dim3(TOK/64, EMBED/64), 256>>>(x, embed_W, embed_b, pe, h, hhb);

    for (int l = 0; l < 3; l++) {
        qkv_hmma<<<dim3(TOK/128, HEADS), 256>>>(
            hhb, wqkvT + (size_t)l*3*HDIM*HDIM, qh, kh, vh);

        attn_mma<<<dim3(SEQ/128, BATCH*HEADS), 256, ATTN_DSMEM>>>(qh, kh, vh, oh);

        gemm_hmma<0,0><<<dim3(EMBED/128, TOK/128), 256, GEMM_DSMEM>>>(
            oh, woT + (size_t)l*EMBED*EMBED, bo + l*EMBED, t1, TOK, EMBED, EMBED);

        ln_kernel<1><<<TOK, 256>>>(t1, h, ln1_g + l*EMBED, ln1_b + l*EMBED, x1, x1h);

        gemm_hmma<1,1><<<dim3(FFN/128, TOK/128), 256, GEMM_DSMEM>>>(
            x1h, w1T + (size_t)l*EMBED*FFN, b1 + l*FFN, ffh, TOK, FFN, EMBED);

        gemm_hmma<0,0><<<dim3(EMBED/128, TOK/128), 256, GEMM_DSMEM>>>(
            ffh, w2T + (size_t)l*FFN*EMBED, b2 + l*EMBED, t2, TOK, EMBED, FFN);

        ln_kernel<1><<<TOK, 256>>>(t2, x1, ln2_g + l*EMBED, ln2_b + l*EMBED, h, hhb);
    }
}

// round 15
// speedup vs baseline: 6.1677x; 1.0548x over previous
#include <cuda_runtime.h>
#include <cuda_fp16.h>
#include <math.h>
#include <stdint.h>

#define SEQ   2048
#define BATCH 2
#define EMBED 1024
#define HEADS 16
#define HDIM  64
#define FFN   4096
#define TOK   (BATCH*SEQ)   /* 4096 tokens */

// ---------------- scratch (device globals; no allocations allowed) ----------
static __device__ __half g_hh [TOK*EMBED];            // half copy of h (QKV input)
static __device__ __half g_qh [TOK*EMBED];            // Q (pre-scaled 1/32) [B,H,S,D]
static __device__ __half g_kh [TOK*EMBED];            // K [B,H,S,D]
static __device__ __half g_vh [TOK*EMBED];            // V [B,H,S,D]
static __device__ float  g_t1 [TOK*EMBED];
static __device__ float  g_x1 [TOK*EMBED];
static __device__ float  g_t2 [TOK*EMBED];
static __device__ __half g_oh [TOK*EMBED];            // attn out (GEMM A)
static __device__ __half g_x1h[TOK*EMBED];            // ln1 out (GEMM A)
static __device__ __half g_ffh[(size_t)TOK*FFN];      // relu(ffn1) (GEMM A)
static __device__ __half g_woT[3*EMBED*EMBED];        // half, k-major BT[n][k]
static __device__ __half g_w1T[(size_t)3*EMBED*FFN];
static __device__ __half g_w2T[(size_t)3*FFN*EMBED];
static __device__ __half g_wqkvT[3*3*HDIM*HDIM];      // [layer][q/k/v][e][d] half

// ---------------------------------------------------------------------------
// helpers
// ---------------------------------------------------------------------------
__device__ __forceinline__ uint32_t smem_u32(const void* p) {
    uint32_t a;
    asm("{ .reg .u64 t; cvta.to.shared.u64 t, %1; cvt.u32.u64 %0, t; }"
        : "=r"(a) : "l"(p));
    return a;
}
__device__ __forceinline__ void ldsm_x4(unsigned* r, uint32_t addr) {
    asm volatile("ldmatrix.sync.aligned.m8n8.x4.shared.b16 {%0,%1,%2,%3}, [%4];"
                 : "=r"(r[0]), "=r"(r[1]), "=r"(r[2]), "=r"(r[3]) : "r"(addr));
}
__device__ __forceinline__ void ldsm_x4_t(unsigned* r, uint32_t addr) {
    asm volatile("ldmatrix.sync.aligned.m8n8.x4.trans.shared.b16 {%0,%1,%2,%3}, [%4];"
                 : "=r"(r[0]), "=r"(r[1]), "=r"(r[2]), "=r"(r[3]) : "r"(addr));
}
__device__ __forceinline__ void mma16816(float* c, const unsigned* a, const unsigned* b) {
    asm volatile(
        "mma.sync.aligned.m16n8k16.row.col.f32.f16.f16.f32 "
        "{%0,%1,%2,%3}, {%4,%5,%6,%7}, {%8,%9}, {%0,%1,%2,%3};"
        : "+f"(c[0]), "+f"(c[1]), "+f"(c[2]), "+f"(c[3])
        : "r"(a[0]), "r"(a[1]), "r"(a[2]), "r"(a[3]), "r"(b[0]), "r"(b[1]));
}
// pack two fp32 into f16x2: lo = x, hi = y
__device__ __forceinline__ uint32_t pack_h2(float x, float y) {
    uint32_t r;
    asm("cvt.rn.f16x2.f32 %0, %1, %2;" : "=r"(r) : "f"(y), "f"(x));
    return r;
}
#define CP_ASYNC16(dst, src) \
    asm volatile("cp.async.cg.shared.global [%0], [%1], 16;" :: "r"(dst), "l"(src) : "memory")
#define CP_COMMIT()  asm volatile("cp.async.commit_group;" ::: "memory")
#define CP_WAIT(n)   asm volatile("cp.async.wait_group %0;" :: "n"(n) : "memory")

// ---------------------------------------------------------------------------
// fp16 mma.sync GEMM, 3-stage cp.async pipeline.
// B fragments now via ldmatrix.x4 (one ldsm covers 2 nt-tiles x 2 k-halves):
//   lane octet g -> matrix (nt = g>>1, k-half = g&1); regs r0..r3 map to
//   bf[nt0]={r0,r1}, bf[nt1]={r2,r3}.
// ---------------------------------------------------------------------------
#define SSTR   56
#define STG_B  (128*SSTR*2)          /* 14336 B per operand stage */
#define GEMM_DSMEM (6*STG_B)         /* 86016 B */

template<int RELU, int OUT_HALF>
__global__ __launch_bounds__(256, 2)
void gemm_hmma(const __half* __restrict__ A, const __half* __restrict__ BT,
               const float* __restrict__ bias, void* __restrict__ Cv,
               int M, int N, int K)
{
    extern __shared__ __align__(16) char dsm[];
    const int tid  = threadIdx.x;
    const int lane = tid & 31, warp = tid >> 5;
    const int m0w = (warp >> 2) * 64;
    const int n0w = (warp & 3) * 32;
    const int rowBase = blockIdx.y * 128;
    const int colBase = blockIdx.x * 128;

    const uint32_t sb = smem_u32(dsm);
    const uint32_t aS = sb;
    const uint32_t bS = sb + 3*STG_B;

    const int lr = tid >> 1, lo = (tid & 1) * 16;
    const __half* Ag = A  + (size_t)(rowBase + lr) * K + lo;
    const __half* Bg = BT + (size_t)(colBase + lr) * K + lo;
    const uint32_t stOff = lr*(SSTR*2) + lo*2;

    float acc[4][4][4];
    #pragma unroll
    for (int mt = 0; mt < 4; mt++)
        #pragma unroll
        for (int nt = 0; nt < 4; nt++)
            #pragma unroll
            for (int r = 0; r < 4; r++) acc[mt][nt][r] = 0.f;

    #define ISSUE(c, stg)                                   \
    {                                                       \
        const __half* ag = Ag + (size_t)(c)*32;             \
        const __half* bg = Bg + (size_t)(c)*32;             \
        uint32_t ad = aS + (stg)*STG_B + stOff;             \
        uint32_t bd = bS + (stg)*STG_B + stOff;             \
        CP_ASYNC16(ad,      ag);                            \
        CP_ASYNC16(ad + 16, ag + 8);                        \
        CP_ASYNC16(bd,      bg);                            \
        CP_ASYNC16(bd + 16, bg + 8);                        \
        CP_COMMIT();                                        \
    }

    const int NC = K >> 5;
    ISSUE(0, 0);
    ISSUE(1, 1);

    const uint32_t aRow  = m0w + (lane & 15);
    const uint32_t aColB = ((lane >> 4) * 8) * 2;
    // B ldmatrix addressing: octet g covers matrix (nt = g>>1, khalf = g&1)
    const int bg8 = lane >> 3, br8 = lane & 7;
    const uint32_t bLdsmOff =
        (uint32_t)(n0w + (bg8 >> 1)*8 + br8) * (SSTR*2) + (uint32_t)(bg8 & 1) * 16;

    for (int c = 0; c < NC; c++) {
        if (c + 1 < NC) CP_WAIT(1); else CP_WAIT(0);
        __syncthreads();
        if (c + 2 < NC) { const int ns = (c + 2) % 3; ISSUE(c + 2, ns); }

        const int cur = c % 3;
        const uint32_t aSt = aS + cur*STG_B;
        const uint32_t bSt = bS + cur*STG_B + bLdsmOff;
        #pragma unroll
        for (int s = 0; s < 2; s++) {
            const uint32_t k0B = s * 32;
            unsigned af[4][4], bf01[4], bf23[4];
            #pragma unroll
            for (int mt = 0; mt < 4; mt++)
                ldsm_x4(af[mt], aSt + (aRow + mt*16)*(SSTR*2) + k0B + aColB);
            ldsm_x4(bf01, bSt + k0B);                     // nt 0,1
            ldsm_x4(bf23, bSt + 16*(SSTR*2) + k0B);       // nt 2,3
            #pragma unroll
            for (int mt = 0; mt < 4; mt++) {
                mma16816(acc[mt][0], af[mt], bf01);
                mma16816(acc[mt][1], af[mt], bf01 + 2);
                mma16816(acc[mt][2], af[mt], bf23);
                mma16816(acc[mt][3], af[mt], bf23 + 2);
            }
        }
    }
    #undef ISSUE

    const int er = lane >> 2, ec = (lane & 3) * 2;
    #pragma unroll
    for (int mt = 0; mt < 4; mt++) {
        const int row = rowBase + m0w + mt*16 + er;
        #pragma unroll
        for (int nt = 0; nt < 4; nt++) {
            const int col = colBase + n0w + nt*8 + ec;
            float2 bv = *(const float2*)(bias + col);
            float v0 = acc[mt][nt][0] + bv.x;
            float v1 = acc[mt][nt][1] + bv.y;
            float v2 = acc[mt][nt][2] + bv.x;
            float v3 = acc[mt][nt][3] + bv.y;
            if (RELU) {
                v0 = fmaxf(v0, 0.f); v1 = fmaxf(v1, 0.f);
                v2 = fmaxf(v2, 0.f); v3 = fmaxf(v3, 0.f);
            }
            if (OUT_HALF) {
                __half* C = (__half*)Cv;
                *(unsigned*)&C[(size_t)row*N + col]     = pack_h2(v0, v1);
                *(unsigned*)&C[(size_t)(row+8)*N + col] = pack_h2(v2, v3);
            } else {
                float* C = (float*)Cv;
                *(float2*)&C[(size_t)row*N + col]     = make_float2(v0, v1);
                *(float2*)&C[(size_t)(row+8)*N + col] = make_float2(v2, v3);
            }
        }
    }
}

// ---------------------------------------------------------------------------
// QKV weight prep (proven)
// ---------------------------------------------------------------------------
__global__ __launch_bounds__(256)
void qkv_wprep(const float* __restrict__ Wq, const float* __restrict__ Wk,
               const float* __restrict__ Wv, __half* __restrict__ out)
{
    const int l = blockIdx.x / 3, m = blockIdx.x % 3;
    const float* W = (m == 0 ? Wq : (m == 1 ? Wk : Wv)) + l*HDIM*HDIM;
    __half* dst = out + ((size_t)l*3 + m)*HDIM*HDIM;
    for (int i = threadIdx.x; i < HDIM*HDIM; i += blockDim.x) {
        int d = i >> 6, e = i & 63;
        dst[e*HDIM + d] = __float2half(W[d*HDIM + e]);
    }
}

// ---------------------------------------------------------------------------
// QKV via fp16 mma (proven)
// ---------------------------------------------------------------------------
#define QPAD 72
__global__ __launch_bounds__(256)
void qkv_hmma(const __half* __restrict__ hh, const __half* __restrict__ WT,
              __half* __restrict__ Q, __half* __restrict__ K, __half* __restrict__ V)
{
    __shared__ __align__(16) __half As[128][QPAD];
    __shared__ __align__(16) __half Ws[192][QPAD];
    const int tid = threadIdx.x, lane = tid & 31, warp = tid >> 5;
    const int t0 = blockIdx.x * 128, head = blockIdx.y;

    {
        const int lr = tid >> 1, lc = (tid & 1) * 32;
        const __half* src = hh + (size_t)(t0 + lr)*EMBED + head*HDIM + lc;
        const uint32_t dst = smem_u32(&As[lr][lc]);
        CP_ASYNC16(dst,      src);
        CP_ASYNC16(dst + 16, src + 8);
        CP_ASYNC16(dst + 32, src + 16);
        CP_ASYNC16(dst + 48, src + 24);
    }
    #pragma unroll
    for (int j = 0; j < 6; j++) {
        const int ci = tid + 256*j;
        const int row = ci >> 3, off = (ci & 7) * 8;
        CP_ASYNC16(smem_u32(&Ws[row][off]), WT + row*HDIM + off);
    }
    CP_COMMIT(); CP_WAIT(0);
    __syncthreads();

    unsigned af[4][4];
    const uint32_t aB = smem_u32(&As[0][0]);
    const uint32_t aRow = warp*16 + (lane & 15);
    const uint32_t aColB = (lane >> 4) * 16;
    #pragma unroll
    for (int kc = 0; kc < 4; kc++)
        ldsm_x4(af[kc], aB + aRow*(QPAD*2) + kc*32 + aColB);

    const int bRow = lane >> 2, bColB = (lane & 3) * 4;
    const int er = lane >> 2, ec = (lane & 3) * 2;
    const int t = t0 + warp*16 + er;
    const int n = t >> 11, s = t & (SEQ - 1);
    __half* outs[3] = {Q, K, V};

    #pragma unroll
    for (int m = 0; m < 3; m++) {
        float acc[8][4];
        #pragma unroll
        for (int nt = 0; nt < 8; nt++)
            #pragma unroll
            for (int r = 0; r < 4; r++) acc[nt][r] = 0.f;

        #pragma unroll
        for (int nt = 0; nt < 8; nt++) {
            const char* nb = (const char*)&Ws[m*64 + nt*8 + bRow][0] + bColB;
            #pragma unroll
            for (int kc = 0; kc < 4; kc++) {
                unsigned b[2];
                b[0] = *(const unsigned*)(nb + kc*32);
                b[1] = *(const unsigned*)(nb + kc*32 + 16);
                mma16816(acc[nt], af[kc], b);
            }
        }

        const float sc = (m == 0) ? 0.03125f : 1.0f;
        __half* base  = outs[m] + ((size_t)(n*HEADS + head)*SEQ + s)*HDIM;
        __half* base8 = base + 8*HDIM;
        #pragma unroll
        for (int nt = 0; nt < 8; nt++) {
            const int col = nt*8 + ec;
            *(unsigned*)(base  + col) = pack_h2(acc[nt][0]*sc, acc[nt][1]*sc);
            *(unsigned*)(base8 + col) = pack_h2(acc[nt][2]*sc, acc[nt][3]*sc);
        }
    }
}

// ---------------------------------------------------------------------------
// fp16 mma.sync flash attention, 128 q-rows/CTA (R14, proven)
// ---------------------------------------------------------------------------
#define APAD 72
#define AROWB (APAD*2)      /* 144 B row stride */
#define ATTN_QS    0
#define ATTN_KS    (128*AROWB)                 /* 18432 */
#define ATTN_VS    (ATTN_KS + 2*64*AROWB)      /* 36864 */
#define ATTN_DSMEM (ATTN_VS + 2*64*AROWB)      /* 55296 */

__global__ __launch_bounds__(256)
void attn_mma(const __half* __restrict__ Q, const __half* __restrict__ K,
              const __half* __restrict__ V, __half* __restrict__ O)
{
    extern __shared__ __align__(16) char asm_[];
    const uint32_t sb = smem_u32(asm_);
    const uint32_t qB0 = sb + ATTN_QS;
    const uint32_t kB0 = sb + ATTN_KS;
    const uint32_t vB0 = sb + ATTN_VS;
    const uint32_t stgB = 64*AROWB;

    const int tid  = threadIdx.x;
    const int lane = tid & 31, warp = tid >> 5;
    const int qt = blockIdx.x, bh = blockIdx.y;

    const int qlr = tid >> 1, qlc = (tid & 1) * 32;
    const int klr = tid >> 2, klc = (tid & 3) * 16;

    {
        const __half* qg = Q + ((size_t)bh*SEQ + qt*128 + qlr)*HDIM + qlc;
        const uint32_t qd = qB0 + qlr*AROWB + qlc*2;
        CP_ASYNC16(qd,      qg);
        CP_ASYNC16(qd + 16, qg + 8);
        CP_ASYNC16(qd + 32, qg + 16);
        CP_ASYNC16(qd + 48, qg + 24);
        const __half* kg = K + ((size_t)bh*SEQ + klr)*HDIM + klc;
        const __half* vg = V + ((size_t)bh*SEQ + klr)*HDIM + klc;
        const uint32_t kd = kB0 + klr*AROWB + klc*2;
        const uint32_t vd = vB0 + klr*AROWB + klc*2;
        CP_ASYNC16(kd,      kg);
        CP_ASYNC16(kd + 16, kg + 8);
        CP_ASYNC16(vd,      vg);
        CP_ASYNC16(vd + 16, vg + 8);
        CP_COMMIT();
    }

    float sacc[8][4], oacc[8][4];
    float mr0 = -1e30f, mr1 = -1e30f, lr0 = 0.f, lr1 = 0.f;
    #pragma unroll
    for (int nt = 0; nt < 8; nt++)
        #pragma unroll
        for (int r = 0; r < 4; r++) oacc[nt][r] = 0.f;

    unsigned qf[4][4];
    const uint32_t aRow  = warp*16 + (lane & 15);
    const uint32_t aColB = (lane >> 4) * 16;
    const int bRow = lane >> 2;
    const int bColB = (lane & 3) * 4;

    const int NT = SEQ / 64;
    for (int kt = 0; kt < NT; kt++) {
        const int cur = kt & 1;
        if (kt + 1 < NT) {
            const __half* kg = K + ((size_t)bh*SEQ + (kt+1)*64 + klr)*HDIM + klc;
            const __half* vg = V + ((size_t)bh*SEQ + (kt+1)*64 + klr)*HDIM + klc;
            const uint32_t kd = kB0 + (cur^1)*stgB + klr*AROWB + klc*2;
            const uint32_t vd = vB0 + (cur^1)*stgB + klr*AROWB + klc*2;
            CP_ASYNC16(kd,      kg);
            CP_ASYNC16(kd + 16, kg + 8);
            CP_ASYNC16(vd,      vg);
            CP_ASYNC16(vd + 16, vg + 8);
            CP_COMMIT();
            CP_WAIT(1);
        } else {
            CP_WAIT(0);
        }
        __syncthreads();

        if (kt == 0) {
            #pragma unroll
            for (int kc = 0; kc < 4; kc++)
                ldsm_x4(qf[kc], qB0 + aRow*AROWB + kc*32 + aColB);
        }

        // ---- S = Q K^T ----
        const uint32_t kB = kB0 + cur*stgB;
        #pragma unroll
        for (int nt = 0; nt < 8; nt++) {
            #pragma unroll
            for (int r = 0; r < 4; r++) sacc[nt][r] = 0.f;
            const uint32_t nb = kB + (nt*8 + bRow)*AROWB + bColB;
            #pragma unroll
            for (int kc = 0; kc < 4; kc++) {
                unsigned b[2];
                asm volatile("ld.shared.u32 %0, [%1];" : "=r"(b[0]) : "r"(nb + kc*32));
                asm volatile("ld.shared.u32 %0, [%1];" : "=r"(b[1]) : "r"(nb + kc*32 + 16));
                mma16816(sacc[nt], qf[kc], b);
            }
        }

        // ---- online softmax ----
        float mx0 = -1e30f, mx1 = -1e30f;
        #pragma unroll
        for (int nt = 0; nt < 8; nt++) {
            mx0 = fmaxf(mx0, fmaxf(sacc[nt][0], sacc[nt][1]));
            mx1 = fmaxf(mx1, fmaxf(sacc[nt][2], sacc[nt][3]));
        }
        mx0 = fmaxf(mx0, __shfl_xor_sync(0xffffffffu, mx0, 1));
        mx0 = fmaxf(mx0, __shfl_xor_sync(0xffffffffu, mx0, 2));
        mx1 = fmaxf(mx1, __shfl_xor_sync(0xffffffffu, mx1, 1));
        mx1 = fmaxf(mx1, __shfl_xor_sync(0xffffffffu, mx1, 2));
        const float nm0 = fmaxf(mr0, mx0), nm1 = fmaxf(mr1, mx1);
        const float fac0 = __expf(mr0 - nm0), fac1 = __expf(mr1 - nm1);
        float sum0 = 0.f, sum1 = 0.f;
        #pragma unroll
        for (int nt = 0; nt < 8; nt++) {
            sacc[nt][0] = __expf(sacc[nt][0] - nm0);
            sacc[nt][1] = __expf(sacc[nt][1] - nm0);
            sacc[nt][2] = __expf(sacc[nt][2] - nm1);
            sacc[nt][3] = __expf(sacc[nt][3] - nm1);
            sum0 += sacc[nt][0] + sacc[nt][1];
            sum1 += sacc[nt][2] + sacc[nt][3];
        }
        sum0 += __shfl_xor_sync(0xffffffffu, sum0, 1);
        sum0 += __shfl_xor_sync(0xffffffffu, sum0, 2);
        sum1 += __shfl_xor_sync(0xffffffffu, sum1, 1);
        sum1 += __shfl_xor_sync(0xffffffffu, sum1, 2);
        lr0 = lr0*fac0 + sum0;  mr0 = nm0;
        lr1 = lr1*fac1 + sum1;  mr1 = nm1;
        #pragma unroll
        for (int nt = 0; nt < 8; nt++) {
            oacc[nt][0] *= fac0; oacc[nt][1] *= fac0;
            oacc[nt][2] *= fac1; oacc[nt][3] *= fac1;
        }

        // ---- P: C-frag -> A-frag ----
        unsigned pa[4][4];
        #pragma unroll
        for (int sc = 0; sc < 4; sc++) {
            pa[sc][0] = pack_h2(sacc[2*sc  ][0], sacc[2*sc  ][1]);
            pa[sc][1] = pack_h2(sacc[2*sc  ][2], sacc[2*sc  ][3]);
            pa[sc][2] = pack_h2(sacc[2*sc+1][0], sacc[2*sc+1][1]);
            pa[sc][3] = pack_h2(sacc[2*sc+1][2], sacc[2*sc+1][3]);
        }

        // ---- O += P V ----
        const uint32_t vB = vB0 + cur*stgB;
        const int g = lane >> 3, r8 = lane & 7;
        #pragma unroll
        for (int sc = 0; sc < 4; sc++) {
            #pragma unroll
            for (int dp = 0; dp < 4; dp++) {
                const uint32_t addr = vB
                    + (sc*16 + ((g & 1) ? 8 : 0) + r8)*AROWB
                    + (dp*16 + ((g >> 1) ? 8 : 0))*2;
                unsigned vf[4];
                ldsm_x4_t(vf, addr);
                mma16816(oacc[2*dp  ], pa[sc], vf);
                mma16816(oacc[2*dp+1], pa[sc], vf + 2);
            }
        }
        __syncthreads();
    }

    const int n = bh >> 4, hh = bh & 15;
    const float i0 = 1.f / lr0, i1 = 1.f / lr1;
    const int row0 = qt*128 + warp*16 + (lane >> 2);
    const int t0 = n*SEQ + row0, t1 = t0 + 8;
    #pragma unroll
    for (int dt = 0; dt < 8; dt++) {
        const int col = hh*HDIM + dt*8 + (lane & 3)*2;
        *(unsigned*)&O[(size_t)t0*EMBED + col] = pack_h2(oacc[dt][0]*i0, oacc[dt][1]*i0);
        *(unsigned*)&O[(size_t)t1*EMBED + col] = pack_h2(oacc[dt][2]*i1, oacc[dt][3]*i1);
    }
}

// ---------------------------------------------------------------------------
// 32x32 tiled transpose + fp16 convert
// ---------------------------------------------------------------------------
__global__ __launch_bounds__(256)
void transpose_h(const float* __restrict__ src, __half* __restrict__ dst, int R, int C)
{
    __shared__ float t[32][33];
    const float* s = src + (size_t)blockIdx.z * R * C;
    __half*      d = dst + (size_t)blockIdx.z * R * C;
    int x  = blockIdx.x*32 + threadIdx.x;
    int y0 = blockIdx.y*32;
    #pragma unroll
    for (int j = 0; j < 4; j++)
        t[threadIdx.y + 8*j][threadIdx.x] = s[(size_t)(y0 + threadIdx.y + 8*j)*C + x];
    __syncthreads();
    int x2 = blockIdx.y*32 + threadIdx.x;
    int y2 = blockIdx.x*32;
    #pragma unroll
    for (int j = 0; j < 4; j++)
        d[(size_t)(y2 + threadIdx.y + 8*j)*R + x2] = __float2half(t[threadIdx.x][threadIdx.y + 8*j]);
}

// ---------------------------------------------------------------------------
// Embed: out = x @ W + b + pe (float), plus half copy for QKV
// ---------------------------------------------------------------------------
__global__ __launch_bounds__(256)
void embed_kernel(const float* __restrict__ X, const float* __restrict__ W,
                  const float* __restrict__ bias, const float* __restrict__ pe,
                  float* __restrict__ out, __half* __restrict__ outh)
{
    __shared__ float Xs[64][64];
    __shared__ float Ws[64][64];
    const int tid = threadIdx.x;
    const int tx = tid & 15, ty = tid >> 4;
    const int t0 = blockIdx.x * 64;
    const int c0 = blockIdx.y * 64;

    {
        const int r = tid >> 2, o4 = (tid & 3) * 16;
        const float* xp = X + (size_t)(t0 + r) * 64 + o4;
        const float* wp = W + (size_t)r * EMBED + c0 + o4;
        #pragma unroll
        for (int u = 0; u < 4; u++) {
            *(float4*)&Xs[r][o4 + 4*u] = *(const float4*)(xp + 4*u);
            *(float4*)&Ws[r][o4 + 4*u] = *(const float4*)(wp + 4*u);
        }
    }
    __syncthreads();

    float acc[4][4];
    #pragma unroll
    for (int i = 0; i < 4; i++)
        #pragma unroll
        for (int j = 0; j < 4; j++) acc[i][j] = 0.f;

    #pragma unroll 8
    for (int d = 0; d < 64; d++) {
        float4 wv = *(const float4*)&Ws[d][tx*4];
        #pragma unroll
        for (int i = 0; i < 4; i++) {
            float xr = Xs[ty*4 + i][d];
            acc[i][0] += xr * wv.x;
            acc[i][1] += xr * wv.y;
            acc[i][2] += xr * wv.z;
            acc[i][3] += xr * wv.w;
        }
    }

    float4 bv = *(const float4*)(bias + c0 + tx*4);
    #pragma unroll
    for (int i = 0; i < 4; i++) {
        int t = t0 + ty*4 + i;
        int s = t & (SEQ - 1);
        float4 pv = *(const float4*)(pe + (size_t)s*EMBED + c0 + tx*4);
        float4 r;
        r.x = acc[i][0] + bv.x + pv.x;
        r.y = acc[i][1] + bv.y + pv.y;
        r.z = acc[i][2] + bv.z + pv.z;
        r.w = acc[i][3] + bv.w + pv.w;
        *(float4*)(out + (size_t)t*EMBED + c0 + tx*4) = r;
        uint2 hv;
        hv.x = pack_h2(r.x, r.y);
        hv.y = pack_h2(r.z, r.w);
        *(uint2*)(outh + (size_t)t*EMBED + c0 + tx*4) = hv;
    }
}

// ---------------------------------------------------------------------------
// Fused residual + LayerNorm (+ optional fp16 copy)
// ---------------------------------------------------------------------------
template<int EMIT_H>
__global__ __launch_bounds__(256)
void ln_kernel(const float* __restrict__ A, const float* __restrict__ R,
               const float* __restrict__ gma, const float* __restrict__ bta,
               float* __restrict__ out, __half* __restrict__ outh)
{
    __shared__ float s1[8], s2[8];
    const int t = blockIdx.x, tid = threadIdx.x;
    const size_t base = (size_t)t * EMBED + tid * 4;

    float4 a = *(const float4*)(A + base);
    float4 r = *(const float4*)(R + base);
    float v0 = a.x + r.x, v1 = a.y + r.y, v2 = a.z + r.z, v3 = a.w + r.w;
    float sum = v0 + v1 + v2 + v3;
    float sq  = v0*v0 + v1*v1 + v2*v2 + v3*v3;

    #pragma unroll
    for (int off = 16; off > 0; off >>= 1) {
        sum += __shfl_xor_sync(0xffffffffu, sum, off);
        sq  += __shfl_xor_sync(0xffffffffu, sq,  off);
    }
    if ((tid & 31) == 0) { s1[tid >> 5] = sum; s2[tid >> 5] = sq; }
    __syncthreads();
    if (tid < 32) {
        float ss = (tid < 8) ? s1[tid] : 0.f;
        float qq = (tid < 8) ? s2[tid] : 0.f;
        #pragma unroll
        for (int off = 4; off > 0; off >>= 1) {
            ss += __shfl_xor_sync(0xffffffffu, ss, off);
            qq += __shfl_xor_sync(0xffffffffu, qq, off);
        }
        if (tid == 0) { s1[0] = ss; s2[0] = qq; }
    }
    __syncthreads();

    const float inv = 1.f / (float)EMBED;
    float mu  = s1[0] * inv;
    float var = s2[0] * inv - mu*mu;
    float rstd = rsqrtf(var + 1e-5f);

    float4 g = *(const float4*)(gma + tid*4);
    float4 b = *(const float4*)(bta + tid*4);
    float4 o;
    o.x = (v0 - mu)*rstd*g.x + b.x;
    o.y = (v1 - mu)*rstd*g.y + b.y;
    o.z = (v2 - mu)*rstd*g.z + b.z;
    o.w = (v3 - mu)*rstd*g.w + b.w;
    *(float4*)(out + base) = o;
    if (EMIT_H) {
        uint2 hv;
        hv.x = pack_h2(o.x, o.y);
        hv.y = pack_h2(o.z, o.w);
        *(uint2*)(outh + base) = hv;
    }
}

// ---------------------------------------------------------------------------
extern "C" void kernel_launch(void* const* d_in, const int* in_sizes, int n_in,
                              void* d_out, int out_size)
{
    const float* x       = (const float*)d_in[0];
    // d_in[1] = mask: all-true -> no-op
    const float* embed_W = (const float*)d_in[2];
    const float* embed_b = (const float*)d_in[3];
    const float* pe      = (const float*)d_in[4];
    const float* Wq      = (const float*)d_in[5];
    const float* Wk      = (const float*)d_in[6];
    const float* Wv      = (const float*)d_in[7];
    const float* Wo      = (const float*)d_in[8];
    const float* bo      = (const float*)d_in[9];
    const float* ln1_g   = (const float*)d_in[10];
    const float* ln1_b   = (const float*)d_in[11];
    const float* W1      = (const float*)d_in[12];
    const float* b1      = (const float*)d_in[13];
    const float* W2      = (const float*)d_in[14];
    const float* b2      = (const float*)d_in[15];
    const float* ln2_g   = (const float*)d_in[16];
    const float* ln2_b   = (const float*)d_in[17];
    float* h = (float*)d_out;

    float  *t1, *x1, *t2;
    __half *hhb, *qh, *kh, *vh, *oh, *x1h, *ffh, *woT, *w1T, *w2T, *wqkvT;
    cudaGetSymbolAddress((void**)&hhb, g_hh);
    cudaGetSymbolAddress((void**)&qh,  g_qh);
    cudaGetSymbolAddress((void**)&kh,  g_kh);
    cudaGetSymbolAddress((void**)&vh,  g_vh);
    cudaGetSymbolAddress((void**)&t1,  g_t1);
    cudaGetSymbolAddress((void**)&x1,  g_x1);
    cudaGetSymbolAddress((void**)&t2,  g_t2);
    cudaGetSymbolAddress((void**)&oh,  g_oh);
    cudaGetSymbolAddress((void**)&x1h, g_x1h);
    cudaGetSymbolAddress((void**)&ffh, g_ffh);
    cudaGetSymbolAddress((void**)&woT, g_woT);
    cudaGetSymbolAddress((void**)&w1T, g_w1T);
    cudaGetSymbolAddress((void**)&w2T, g_w2T);
    cudaGetSymbolAddress((void**)&wqkvT, g_wqkvT);

    cudaFuncSetAttribute(gemm_hmma<0,0>, cudaFuncAttributeMaxDynamicSharedMemorySize, GEMM_DSMEM);
    cudaFuncSetAttribute(gemm_hmma<1,1>, cudaFuncAttributeMaxDynamicSharedMemorySize, GEMM_DSMEM);
    cudaFuncSetAttribute(attn_mma, cudaFuncAttributeMaxDynamicSharedMemorySize, ATTN_DSMEM);

    transpose_h<<<dim3(EMBED/32, EMBED/32, 3), dim3(32,8)>>>(Wo, woT, EMBED, EMBED);
    transpose_h<<<dim3(FFN/32,   EMBED/32, 3), dim3(32,8)>>>(W1, w1T, EMBED, FFN);
    transpose_h<<<dim3(EMBED/32, FFN/32,   3), dim3(32,8)>>>(W2, w2T, FFN, EMBED);
    qkv_wprep<<<9, 256>>>(Wq, Wk, Wv, wqkvT);

    embed_kernel<<<dim3(TOK/64, EMBED/64), 256>>>(x, embed_W, embed_b, pe, h, hhb);

    for (int l = 0; l < 3; l++) {
        qkv_hmma<<<dim3(TOK/128, HEADS), 256>>>(
            hhb, wqkvT + (size_t)l*3*HDIM*HDIM, qh, kh, vh);

        attn_mma<<<dim3(SEQ/128, BATCH*HEADS), 256, ATTN_DSMEM>>>(qh, kh, vh, oh);

        gemm_hmma<0,0><<<dim3(EMBED/128, TOK/128), 256, GEMM_DSMEM>>>(
            oh, woT + (size_t)l*EMBED*EMBED, bo + l*EMBED, t1, TOK, EMBED, EMBED);

        ln_kernel<1><<<TOK, 256>>>(t1, h, ln1_g + l*EMBED, ln1_b + l*EMBED, x1, x1h);

        gemm_hmma<1,1><<<dim3(FFN/128, TOK/128), 256, GEMM_DSMEM>>>(
            x1h, w1T + (size_t)l*EMBED*FFN, b1 + l*FFN, ffh, TOK, FFN, EMBED);

        gemm_hmma<0,0><<<dim3(EMBED/128, TOK/128), 256, GEMM_DSMEM>>>(
            ffh, w2T + (size_t)l*FFN*EMBED, b2 + l*EMBED, t2, TOK, EMBED, FFN);

        ln_kernel<1><<<TOK, 256>>>(t2, x1, ln2_g + l*EMBED, ln2_b + l*EMBED, h, hhb);
    }
}